// round 2
// baseline (speedup 1.0000x reference)
#include <cuda_runtime.h>
#include <math.h>

#define N_NODES  50000
#define N_EDGES  800000
#define N_GRAPHS 2048
#define NE_TOT   (N_EDGES + N_NODES)
#define F0 78
#define F1 78
#define F2 156
#define F3 312

// ---------------- scratch (device globals; no allocation allowed) ----------------
__device__ float g_h[N_NODES * F3];        // GEMM output (pre-aggregation features)
__device__ float g_y[N_NODES * F3];        // conv output (post aggregation+bias+relu)
__device__ int   g_count[N_NODES];         // in-degree + self-loop
__device__ float g_dinv[N_NODES];          // 1/sqrt(deg)
__device__ int   g_rowptr[N_NODES + 1];
__device__ int   g_cursor[N_NODES];
__device__ int   g_csrc[NE_TOT];           // CSR (by dst): source node ids
__device__ float g_cw[NE_TOT];             // CSR edge weights dinv[s]*dinv[d]
__device__ float g_pool[N_GRAPHS * F3];
__device__ float g_m1[N_GRAPHS * 1024];
__device__ float g_m2[N_GRAPHS * 1024];
__device__ int   g_src[N_EDGES];
__device__ int   g_dst[N_EDGES];
__device__ int   g_batch[N_NODES];
__device__ int   g_is64;

// ---------------- dtype detection: int64 edge data has all odd 32-bit words == 0
__global__ void detect_kernel(const int* __restrict__ ei32) {
    __shared__ int sh[256];
    int t = threadIdx.x;
    int orv = 0;
    for (int i = t; i < 2048; i += 256) orv |= ei32[2 * i + 1];
    sh[t] = orv;
    __syncthreads();
    for (int o = 128; o; o >>= 1) {
        if (t < o) sh[t] |= sh[t + o];
        __syncthreads();
    }
    if (t == 0) g_is64 = (sh[0] == 0) ? 1 : 0;
}

__global__ void convert_edges_kernel(const void* __restrict__ ei) {
    int e = blockIdx.x * blockDim.x + threadIdx.x;
    if (e >= N_EDGES) return;
    if (g_is64) {
        const long long* p = (const long long*)ei;
        g_src[e] = (int)p[e];
        g_dst[e] = (int)p[N_EDGES + e];
    } else {
        const int* p = (const int*)ei;
        g_src[e] = p[e];
        g_dst[e] = p[N_EDGES + e];
    }
}

__global__ void convert_batch_kernel(const void* __restrict__ b) {
    int i = blockIdx.x * blockDim.x + threadIdx.x;
    if (i >= N_NODES) return;
    g_batch[i] = g_is64 ? (int)((const long long*)b)[i] : ((const int*)b)[i];
}

// ---------------- graph preprocessing ----------------
__global__ void init_kernel() {
    int i = blockIdx.x * blockDim.x + threadIdx.x;
    if (i < N_NODES) g_count[i] = 1;                 // self loop
    if (i < N_GRAPHS * F3) g_pool[i] = 0.0f;         // pool identity (values >= 0 post-relu)
}

__global__ void hist_kernel() {
    int e = blockIdx.x * blockDim.x + threadIdx.x;
    if (e >= N_EDGES) return;
    atomicAdd(&g_count[g_dst[e]], 1);
}

__global__ void dinv_kernel() {
    int i = blockIdx.x * blockDim.x + threadIdx.x;
    if (i < N_NODES) g_dinv[i] = rsqrtf((float)g_count[i]);
}

// single-block exclusive scan of g_count -> g_rowptr (+ copy to g_cursor)
__global__ void scan_kernel() {
    __shared__ int sums[1024];
    const int CH = (N_NODES + 1023) / 1024;
    int t = threadIdx.x;
    int base = t * CH;
    int s = 0;
    for (int i = 0; i < CH; i++) {
        int idx = base + i;
        if (idx < N_NODES) s += g_count[idx];
    }
    sums[t] = s;
    __syncthreads();
    for (int off = 1; off < 1024; off <<= 1) {
        int v = (t >= off) ? sums[t - off] : 0;
        __syncthreads();
        sums[t] += v;
        __syncthreads();
    }
    int run = (t == 0) ? 0 : sums[t - 1];
    for (int i = 0; i < CH; i++) {
        int idx = base + i;
        if (idx < N_NODES) {
            g_rowptr[idx] = run;
            g_cursor[idx] = run;
            run += g_count[idx];
        }
    }
    if (t == 1023) g_rowptr[N_NODES] = sums[1023];
}

__global__ void fill_edges_kernel() {
    int e = blockIdx.x * blockDim.x + threadIdx.x;
    if (e >= N_EDGES) return;
    int s = g_src[e];
    int d = g_dst[e];
    int p = atomicAdd(&g_cursor[d], 1);
    g_csrc[p] = s;
    g_cw[p] = g_dinv[s] * g_dinv[d];
}

__global__ void fill_self_kernel() {
    int i = blockIdx.x * blockDim.x + threadIdx.x;
    if (i >= N_NODES) return;
    int p = atomicAdd(&g_cursor[i], 1);
    g_csrc[p] = i;
    float di = g_dinv[i];
    g_cw[p] = di * di;
}

// ---------------- generic tiled fp32 GEMM: C = act(A[M,K] @ B[K,N] + bias) ----------------
__global__ void gemm_kernel(const float* __restrict__ A, const float* __restrict__ B,
                            const float* __restrict__ bias, float* __restrict__ C,
                            int M, int N, int K, int relu)
{
    __shared__ float As[16][68];
    __shared__ float Bs[16][68];
    int tid = threadIdx.x;             // 256 threads
    int tr = tid >> 4, tc = tid & 15;  // 16x16, each thread 4x4 outputs
    int rowBase = blockIdx.y * 64;
    int colBase = blockIdx.x * 64;
    float acc[4][4] = {};

    for (int k0 = 0; k0 < K; k0 += 16) {
        #pragma unroll
        for (int i = 0; i < 4; i++) {
            int l = tid + 256 * i;           // A tile: 64 rows x 16 k
            int ar = l >> 4, ak = l & 15;
            int gr = rowBase + ar, gk = k0 + ak;
            As[ak][ar] = (gr < M && gk < K) ? A[(size_t)gr * K + gk] : 0.0f;
        }
        #pragma unroll
        for (int i = 0; i < 4; i++) {
            int l = tid + 256 * i;           // B tile: 16 k x 64 cols
            int br = l >> 6, bc = l & 63;
            int gk = k0 + br, gc = colBase + bc;
            Bs[br][bc] = (gk < K && gc < N) ? B[(size_t)gk * N + gc] : 0.0f;
        }
        __syncthreads();
        #pragma unroll
        for (int kk = 0; kk < 16; kk++) {
            float a[4], b[4];
            #pragma unroll
            for (int i = 0; i < 4; i++) a[i] = As[kk][tr * 4 + i];
            #pragma unroll
            for (int j = 0; j < 4; j++) b[j] = Bs[kk][tc * 4 + j];
            #pragma unroll
            for (int i = 0; i < 4; i++)
                #pragma unroll
                for (int j = 0; j < 4; j++)
                    acc[i][j] = fmaf(a[i], b[j], acc[i][j]);
        }
        __syncthreads();
    }

    #pragma unroll
    for (int i = 0; i < 4; i++) {
        int r = rowBase + tr * 4 + i;
        if (r >= M) continue;
        #pragma unroll
        for (int j = 0; j < 4; j++) {
            int c = colBase + tc * 4 + j;
            if (c >= N) continue;
            float v = acc[i][j];
            if (bias) v += bias[c];
            if (relu) v = fmaxf(v, 0.0f);
            C[(size_t)r * N + c] = v;
        }
    }
}

// ---------------- GCN aggregation: out[d] = relu( bias + sum_e w_e * h[src_e] ) ----------------
// one warp per (node, 32-col chunk); CSR includes the self loop.
__global__ void conv_kernel(const float* __restrict__ h, const float* __restrict__ bias,
                            float* __restrict__ out, int F)
{
    int node = blockIdx.x * blockDim.y + threadIdx.y;
    if (node >= N_NODES) return;
    int c = blockIdx.y * 32 + threadIdx.x;
    bool valid = c < F;
    int k0 = g_rowptr[node], k1 = g_rowptr[node + 1];
    float acc0 = 0.0f, acc1 = 0.0f;
    int k = k0;
    for (; k + 1 < k1; k += 2) {
        int sA = g_csrc[k], sB = g_csrc[k + 1];
        float wA = g_cw[k], wB = g_cw[k + 1];
        if (valid) {
            acc0 = fmaf(h[(size_t)sA * F + c], wA, acc0);
            acc1 = fmaf(h[(size_t)sB * F + c], wB, acc1);
        }
    }
    if (k < k1 && valid) {
        acc0 = fmaf(h[(size_t)g_csrc[k] * F + c], g_cw[k], acc0);
    }
    if (valid) out[(size_t)node * F + c] = fmaxf(acc0 + acc1 + bias[c], 0.0f);
}

// ---------------- global max pool (int-bits atomicMax; values >= 0) ----------------
__global__ void pool_kernel(const float* __restrict__ h)
{
    int node = blockIdx.x * blockDim.y + threadIdx.y;
    if (node >= N_NODES) return;
    int c = blockIdx.y * 32 + threadIdx.x;
    if (c >= F3) return;
    int g = g_batch[node];
    float v = h[(size_t)node * F3 + c];
    atomicMax((int*)&g_pool[(size_t)g * F3 + c], __float_as_int(v));
}

// ---------------- final 512 -> 1 dot + sigmoid ----------------
__global__ void final_kernel(const float* __restrict__ c2, const float* __restrict__ Wo,
                             const float* __restrict__ bo, float* __restrict__ out)
{
    int row = blockIdx.x * blockDim.y + threadIdx.y;
    if (row >= N_GRAPHS) return;
    int lane = threadIdx.x;
    float s = 0.0f;
    for (int k = lane; k < 512; k += 32)
        s = fmaf(c2[(size_t)row * 512 + k], Wo[k], s);
    #pragma unroll
    for (int o = 16; o; o >>= 1) s += __shfl_xor_sync(0xFFFFFFFFu, s, o);
    if (lane == 0) out[row] = 1.0f / (1.0f + expf(-(s + bo[0])));
}

// ---------------- launch ----------------
extern "C" void kernel_launch(void* const* d_in, const int* in_sizes, int n_in,
                              void* d_out, int out_size)
{
    const float* x     = (const float*)d_in[0];
    const void*  ei    = d_in[1];
    const void*  batch = d_in[2];
    const float* W1 = (const float*)d_in[3];  const float* b1 = (const float*)d_in[4];
    const float* W2 = (const float*)d_in[5];  const float* b2 = (const float*)d_in[6];
    const float* W3 = (const float*)d_in[7];  const float* b3 = (const float*)d_in[8];
    const float* Wg1 = (const float*)d_in[9];  const float* bg1 = (const float*)d_in[10];
    const float* Wg2 = (const float*)d_in[11]; const float* bg2 = (const float*)d_in[12];
    const float* Wf1 = (const float*)d_in[13]; const float* bf1 = (const float*)d_in[14];
    const float* Wf2 = (const float*)d_in[15]; const float* bf2 = (const float*)d_in[16];
    const float* Wo  = (const float*)d_in[17]; const float* bo  = (const float*)d_in[18];
    float* out = (float*)d_out;

    float *h, *y, *pool, *m1, *m2;
    cudaGetSymbolAddress((void**)&h,    g_h);
    cudaGetSymbolAddress((void**)&y,    g_y);
    cudaGetSymbolAddress((void**)&pool, g_pool);
    cudaGetSymbolAddress((void**)&m1,   g_m1);
    cudaGetSymbolAddress((void**)&m2,   g_m2);

    // dtype detection + conversion (handles int32 or int64 edge/batch data)
    detect_kernel<<<1, 256>>>((const int*)ei);
    convert_edges_kernel<<<(N_EDGES + 255) / 256, 256>>>(ei);
    convert_batch_kernel<<<(N_NODES + 255) / 256, 256>>>(batch);

    // graph preprocessing (per-launch; deterministic work)
    int initN = N_GRAPHS * F3;  // 638976 > N_NODES
    init_kernel<<<(initN + 255) / 256, 256>>>();
    hist_kernel<<<(N_EDGES + 255) / 256, 256>>>();
    dinv_kernel<<<(N_NODES + 255) / 256, 256>>>();
    scan_kernel<<<1, 1024>>>();
    fill_edges_kernel<<<(N_EDGES + 255) / 256, 256>>>();
    fill_self_kernel<<<(N_NODES + 255) / 256, 256>>>();

    auto gemm = [&](const float* A, const float* B, const float* bias, float* C,
                    int M, int N, int K, int relu) {
        dim3 grid((N + 63) / 64, (M + 63) / 64);
        gemm_kernel<<<grid, 256>>>(A, B, bias, C, M, N, K, relu);
    };
    dim3 cb(32, 8);

    // conv layer 1: XD=78 -> 78
    gemm(x, W1, nullptr, h, N_NODES, F1, F0, 0);
    conv_kernel<<<dim3((N_NODES + 7) / 8, (F1 + 31) / 32), cb>>>(h, b1, y, F1);
    // conv layer 2: 78 -> 156
    gemm(y, W2, nullptr, h, N_NODES, F2, F1, 0);
    conv_kernel<<<dim3((N_NODES + 7) / 8, (F2 + 31) / 32), cb>>>(h, b2, y, F2);
    // conv layer 3: 156 -> 312
    gemm(y, W3, nullptr, h, N_NODES, F3, F2, 0);
    conv_kernel<<<dim3((N_NODES + 7) / 8, (F3 + 31) / 32), cb>>>(h, b3, y, F3);

    // global max pool
    pool_kernel<<<dim3((N_NODES + 7) / 8, (F3 + 31) / 32), cb>>>(y);

    // MLP head
    gemm(pool, Wg1, bg1, m1, N_GRAPHS, 1024, F3, 1);
    gemm(m1, Wg2, bg2, m2, N_GRAPHS, 128, 1024, 0);
    gemm(m2, Wf1, bf1, m1, N_GRAPHS, 1024, 128, 1);
    gemm(m1, Wf2, bf2, m2, N_GRAPHS, 512, 1024, 1);
    final_kernel<<<(N_GRAPHS + 7) / 8, cb>>>(m2, Wo, bo, out);
}

// round 3
// speedup vs baseline: 1.1651x; 1.1651x over previous
#include <cuda_runtime.h>
#include <cuda_bf16.h>
#include <math.h>
#include <stdint.h>

#define N_NODES  50000
#define N_EDGES  800000
#define N_GRAPHS 2048
#define NE_TOT   (N_EDGES + N_NODES)
#define F0 78
#define F1 78
#define F2 156
#define F3 312

// ---------------- scratch (device globals) ----------------
__device__ float g_h[N_NODES * F3];        // aggregated features (GEMM input)
__device__ float g_y[N_NODES * F3];        // layer output (post GEMM+bias+relu)
__device__ int   g_count[N_NODES];
__device__ float g_dinv[N_NODES];
__device__ int   g_rowptr[N_NODES + 1];
__device__ int   g_cursor[N_NODES];
__device__ int   g_csrc[NE_TOT];
__device__ float g_cw[NE_TOT];
__device__ float g_pool[N_GRAPHS * F3];
__device__ float g_m1[N_GRAPHS * 1024];
__device__ float g_m2[N_GRAPHS * 1024];
__device__ int   g_src[N_EDGES];
__device__ int   g_dst[N_EDGES];
__device__ int   g_batch[N_NODES];
__device__ int   g_gstart[N_GRAPHS + 1];
__device__ int   g_is64;

// ---------------- dtype detection: int64 edge data has all odd 32-bit words == 0
__global__ void detect_kernel(const int* __restrict__ ei32) {
    __shared__ int sh[256];
    int t = threadIdx.x;
    int orv = 0;
    for (int i = t; i < 2048; i += 256) orv |= ei32[2 * i + 1];
    sh[t] = orv;
    __syncthreads();
    for (int o = 128; o; o >>= 1) {
        if (t < o) sh[t] |= sh[t + o];
        __syncthreads();
    }
    if (t == 0) g_is64 = (sh[0] == 0) ? 1 : 0;
}

__global__ void convert_edges_kernel(const void* __restrict__ ei) {
    int e = blockIdx.x * blockDim.x + threadIdx.x;
    if (e >= N_EDGES) return;
    if (g_is64) {
        const long long* p = (const long long*)ei;
        g_src[e] = (int)p[e];
        g_dst[e] = (int)p[N_EDGES + e];
    } else {
        const int* p = (const int*)ei;
        g_src[e] = p[e];
        g_dst[e] = p[N_EDGES + e];
    }
}

__global__ void convert_batch_kernel(const void* __restrict__ b) {
    int i = blockIdx.x * blockDim.x + threadIdx.x;
    if (i >= N_NODES) return;
    g_batch[i] = g_is64 ? (int)((const long long*)b)[i] : ((const int*)b)[i];
}

// ---------------- graph preprocessing ----------------
__global__ void init_kernel() {
    int i = blockIdx.x * blockDim.x + threadIdx.x;
    if (i < N_NODES) g_count[i] = 1;  // self loop
}

__global__ void hist_kernel() {
    int e = blockIdx.x * blockDim.x + threadIdx.x;
    if (e >= N_EDGES) return;
    atomicAdd(&g_count[g_dst[e]], 1);
}

__global__ void dinv_kernel() {
    int i = blockIdx.x * blockDim.x + threadIdx.x;
    if (i < N_NODES) g_dinv[i] = rsqrtf((float)g_count[i]);
}

__global__ void scan_kernel() {
    __shared__ int sums[1024];
    const int CH = (N_NODES + 1023) / 1024;
    int t = threadIdx.x;
    int base = t * CH;
    int s = 0;
    for (int i = 0; i < CH; i++) {
        int idx = base + i;
        if (idx < N_NODES) s += g_count[idx];
    }
    sums[t] = s;
    __syncthreads();
    for (int off = 1; off < 1024; off <<= 1) {
        int v = (t >= off) ? sums[t - off] : 0;
        __syncthreads();
        sums[t] += v;
        __syncthreads();
    }
    int run = (t == 0) ? 0 : sums[t - 1];
    for (int i = 0; i < CH; i++) {
        int idx = base + i;
        if (idx < N_NODES) {
            g_rowptr[idx] = run;
            g_cursor[idx] = run;
            run += g_count[idx];
        }
    }
    if (t == 1023) g_rowptr[N_NODES] = sums[1023];
}

__global__ void fill_edges_kernel() {
    int e = blockIdx.x * blockDim.x + threadIdx.x;
    if (e >= N_EDGES) return;
    int s = g_src[e];
    int d = g_dst[e];
    int p = atomicAdd(&g_cursor[d], 1);
    g_csrc[p] = s;
    g_cw[p] = g_dinv[s] * g_dinv[d];
}

__global__ void fill_self_kernel() {
    int i = blockIdx.x * blockDim.x + threadIdx.x;
    if (i >= N_NODES) return;
    int p = atomicAdd(&g_cursor[i], 1);
    g_csrc[p] = i;
    float di = g_dinv[i];
    g_cw[p] = di * di;
}

// graph start offsets from sorted batch
__global__ void gstart_kernel() {
    int i = blockIdx.x * blockDim.x + threadIdx.x;
    if (i > N_NODES) return;
    if (i == 0) {
        for (int g = 0; g <= g_batch[0]; g++) g_gstart[g] = 0;
    } else if (i == N_NODES) {
        for (int g = g_batch[N_NODES - 1] + 1; g <= N_GRAPHS; g++) g_gstart[g] = N_NODES;
    } else {
        int b0 = g_batch[i - 1], b1 = g_batch[i];
        for (int g = b0 + 1; g <= b1; g++) g_gstart[g] = i;
    }
}

// ---------------- GCN aggregation (pure): out[d] = sum_e w_e * x[src_e] ----------------
__global__ void agg_kernel(const float* __restrict__ x, float* __restrict__ out, int F)
{
    int node = blockIdx.x * blockDim.y + threadIdx.y;
    if (node >= N_NODES) return;
    int c = blockIdx.y * 32 + threadIdx.x;
    bool valid = c < F;
    int k0 = g_rowptr[node], k1 = g_rowptr[node + 1];
    float acc0 = 0.0f, acc1 = 0.0f;
    int k = k0;
    for (; k + 1 < k1; k += 2) {
        int sA = g_csrc[k], sB = g_csrc[k + 1];
        float wA = g_cw[k], wB = g_cw[k + 1];
        if (valid) {
            acc0 = fmaf(x[(size_t)sA * F + c], wA, acc0);
            acc1 = fmaf(x[(size_t)sB * F + c], wB, acc1);
        }
    }
    if (k < k1 && valid)
        acc0 = fmaf(x[(size_t)g_csrc[k] * F + c], g_cw[k], acc0);
    if (valid) out[(size_t)node * F + c] = acc0 + acc1;
}

// ---------------- tensor-core GEMM: C = act(A[M,K] @ B[K,N] + bias) ----------------
// split-bf16: A = Ah + Al, B = Bh + Bl;  C ≈ Ah·Bh + Ah·Bl + Al·Bh (fp32 accumulate)
#define BM 128
#define BN 64

__device__ __forceinline__ void mma16816(float* c, const uint32_t* a, const uint32_t* b) {
    asm volatile(
        "mma.sync.aligned.m16n8k16.row.col.f32.bf16.bf16.f32 "
        "{%0,%1,%2,%3}, {%4,%5,%6,%7}, {%8,%9}, {%0,%1,%2,%3};\n"
        : "+f"(c[0]), "+f"(c[1]), "+f"(c[2]), "+f"(c[3])
        : "r"(a[0]), "r"(a[1]), "r"(a[2]), "r"(a[3]), "r"(b[0]), "r"(b[1]));
}

__device__ __forceinline__ uint32_t split_pack(float x0, float x1, uint32_t& lo) {
    __nv_bfloat16 h0 = __float2bfloat16(x0);
    __nv_bfloat16 h1 = __float2bfloat16(x1);
    __nv_bfloat16 l0 = __float2bfloat16(x0 - __bfloat162float(h0));
    __nv_bfloat16 l1 = __float2bfloat16(x1 - __bfloat162float(h1));
    lo = ((uint32_t)__bfloat16_as_ushort(l1) << 16) | __bfloat16_as_ushort(l0);
    return ((uint32_t)__bfloat16_as_ushort(h1) << 16) | __bfloat16_as_ushort(h0);
}

__global__ void __launch_bounds__(256) mma_gemm_kernel(
    const float* __restrict__ A, const float* __restrict__ B,
    const float* __restrict__ bias, float* __restrict__ C,
    int M, int N, int K, int relu)
{
    __shared__ uint32_t sAh[BM][9];   // [row][kpair], 8 used + 1 pad
    __shared__ uint32_t sAl[BM][9];
    __shared__ uint32_t sBh[BN][9];   // [col(n)][kpair]
    __shared__ uint32_t sBl[BN][9];

    int tid = threadIdx.x;            // 256
    int warp = tid >> 5, lane = tid & 31;
    int wm = warp >> 1;               // 0..3 : m offset wm*32
    int wn = warp & 1;                // 0..1 : n offset wn*32
    int g = lane >> 2, tg = lane & 3;
    int rowBase = blockIdx.y * BM;
    int colBase = blockIdx.x * BN;

    float acc[2][4][4];
    #pragma unroll
    for (int mt = 0; mt < 2; mt++)
        #pragma unroll
        for (int nt = 0; nt < 4; nt++)
            #pragma unroll
            for (int i = 0; i < 4; i++) acc[mt][nt][i] = 0.0f;

    int rowA = tid >> 1;              // 0..127
    int kA = (tid & 1) * 8;           // 0 or 8
    int nB = tid & 63;                // 0..63
    int kB0 = (tid >> 6) * 2;         // kpair base: 0,2,4,6

    for (int k0 = 0; k0 < K; k0 += 16) {
        __syncthreads();
        // ---- load+convert A tile (128x16) ----
        {
            int gr = rowBase + rowA;
            float av[8];
            #pragma unroll
            for (int j = 0; j < 8; j++) {
                int gk = k0 + kA + j;
                av[j] = (gr < M && gk < K) ? A[(size_t)gr * K + gk] : 0.0f;
            }
            #pragma unroll
            for (int p = 0; p < 4; p++) {
                uint32_t lo;
                uint32_t hi = split_pack(av[2 * p], av[2 * p + 1], lo);
                sAh[rowA][kA / 2 + p] = hi;
                sAl[rowA][kA / 2 + p] = lo;
            }
        }
        // ---- load+convert B tile (16x64, stored n-major) ----
        {
            int gc = colBase + nB;
            #pragma unroll
            for (int p = 0; p < 2; p++) {
                int kp = kB0 + p;
                int gk = k0 + kp * 2;
                float x0 = (gk < K && gc < N) ? B[(size_t)gk * N + gc] : 0.0f;
                float x1 = (gk + 1 < K && gc < N) ? B[(size_t)(gk + 1) * N + gc] : 0.0f;
                uint32_t lo;
                uint32_t hi = split_pack(x0, x1, lo);
                sBh[nB][kp] = hi;
                sBl[nB][kp] = lo;
            }
        }
        __syncthreads();

        // ---- fragments ----
        uint32_t af[2][2][4];   // [split][mt][4]
        #pragma unroll
        for (int mt = 0; mt < 2; mt++) {
            int r0 = wm * 32 + mt * 16 + g;
            af[0][mt][0] = sAh[r0][tg];     af[0][mt][1] = sAh[r0 + 8][tg];
            af[0][mt][2] = sAh[r0][tg + 4]; af[0][mt][3] = sAh[r0 + 8][tg + 4];
            af[1][mt][0] = sAl[r0][tg];     af[1][mt][1] = sAl[r0 + 8][tg];
            af[1][mt][2] = sAl[r0][tg + 4]; af[1][mt][3] = sAl[r0 + 8][tg + 4];
        }
        uint32_t bfr[2][4][2];  // [split][nt][2]
        #pragma unroll
        for (int nt = 0; nt < 4; nt++) {
            int n0 = wn * 32 + nt * 8 + g;
            bfr[0][nt][0] = sBh[n0][tg]; bfr[0][nt][1] = sBh[n0][tg + 4];
            bfr[1][nt][0] = sBl[n0][tg]; bfr[1][nt][1] = sBl[n0][tg + 4];
        }
        #pragma unroll
        for (int mt = 0; mt < 2; mt++)
            #pragma unroll
            for (int nt = 0; nt < 4; nt++) {
                mma16816(acc[mt][nt], af[0][mt], bfr[0][nt]);  // hi*hi
                mma16816(acc[mt][nt], af[0][mt], bfr[1][nt]);  // hi*lo
                mma16816(acc[mt][nt], af[1][mt], bfr[0][nt]);  // lo*hi
            }
    }

    // ---- epilogue ----
    #pragma unroll
    for (int mt = 0; mt < 2; mt++) {
        int r0 = rowBase + wm * 32 + mt * 16 + g;
        #pragma unroll
        for (int nt = 0; nt < 4; nt++) {
            int c0 = colBase + wn * 32 + nt * 8 + tg * 2;
            #pragma unroll
            for (int i = 0; i < 4; i++) {
                int r = r0 + (i >> 1) * 8;
                int c = c0 + (i & 1);
                if (r < M && c < N) {
                    float v = acc[mt][nt][i];
                    if (bias) v += bias[c];
                    if (relu) v = fmaxf(v, 0.0f);
                    C[(size_t)r * N + c] = v;
                }
            }
        }
    }
}

// ---------------- segmented global max pool ----------------
__global__ void pool_kernel(const float* __restrict__ y)
{
    int grp = blockIdx.x * blockDim.y + threadIdx.y;
    if (grp >= N_GRAPHS) return;
    int c = blockIdx.y * 32 + threadIdx.x;
    if (c >= F3) return;
    int s = g_gstart[grp], e = g_gstart[grp + 1];
    float m = 0.0f;  // relu outputs >= 0
    for (int i = s; i < e; i++) m = fmaxf(m, y[(size_t)i * F3 + c]);
    g_pool[(size_t)grp * F3 + c] = m;
}

// ---------------- final 512 -> 1 dot + sigmoid ----------------
__global__ void final_kernel(const float* __restrict__ c2, const float* __restrict__ Wo,
                             const float* __restrict__ bo, float* __restrict__ out)
{
    int row = blockIdx.x * blockDim.y + threadIdx.y;
    if (row >= N_GRAPHS) return;
    int lane = threadIdx.x;
    float s = 0.0f;
    for (int k = lane; k < 512; k += 32)
        s = fmaf(c2[(size_t)row * 512 + k], Wo[k], s);
    #pragma unroll
    for (int o = 16; o; o >>= 1) s += __shfl_xor_sync(0xFFFFFFFFu, s, o);
    if (lane == 0) out[row] = 1.0f / (1.0f + expf(-(s + bo[0])));
}

// ---------------- launch ----------------
extern "C" void kernel_launch(void* const* d_in, const int* in_sizes, int n_in,
                              void* d_out, int out_size)
{
    const float* x     = (const float*)d_in[0];
    const void*  ei    = d_in[1];
    const void*  batch = d_in[2];
    const float* W1 = (const float*)d_in[3];  const float* b1 = (const float*)d_in[4];
    const float* W2 = (const float*)d_in[5];  const float* b2 = (const float*)d_in[6];
    const float* W3 = (const float*)d_in[7];  const float* b3 = (const float*)d_in[8];
    const float* Wg1 = (const float*)d_in[9];  const float* bg1 = (const float*)d_in[10];
    const float* Wg2 = (const float*)d_in[11]; const float* bg2 = (const float*)d_in[12];
    const float* Wf1 = (const float*)d_in[13]; const float* bf1 = (const float*)d_in[14];
    const float* Wf2 = (const float*)d_in[15]; const float* bf2 = (const float*)d_in[16];
    const float* Wo  = (const float*)d_in[17]; const float* bo  = (const float*)d_in[18];
    float* out = (float*)d_out;

    float *h, *y, *pool, *m1, *m2;
    cudaGetSymbolAddress((void**)&h,    g_h);
    cudaGetSymbolAddress((void**)&y,    g_y);
    cudaGetSymbolAddress((void**)&pool, g_pool);
    cudaGetSymbolAddress((void**)&m1,   g_m1);
    cudaGetSymbolAddress((void**)&m2,   g_m2);

    // dtype detect + conversion
    detect_kernel<<<1, 256>>>((const int*)ei);
    convert_edges_kernel<<<(N_EDGES + 255) / 256, 256>>>(ei);
    convert_batch_kernel<<<(N_NODES + 255) / 256, 256>>>(batch);

    // graph preprocessing
    init_kernel<<<(N_NODES + 255) / 256, 256>>>();
    hist_kernel<<<(N_EDGES + 255) / 256, 256>>>();
    dinv_kernel<<<(N_NODES + 255) / 256, 256>>>();
    scan_kernel<<<1, 1024>>>();
    fill_edges_kernel<<<(N_EDGES + 255) / 256, 256>>>();
    fill_self_kernel<<<(N_NODES + 255) / 256, 256>>>();
    gstart_kernel<<<(N_NODES + 256) / 256, 256>>>();

    auto gemm = [&](const float* A, const float* B, const float* bias, float* C,
                    int M, int N, int K, int relu) {
        dim3 grid((N + BN - 1) / BN, (M + BM - 1) / BM);
        mma_gemm_kernel<<<grid, 256>>>(A, B, bias, C, M, N, K, relu);
    };
    dim3 cb(32, 8);

    // layer 1: agg(x) @ W1 + b1, relu
    agg_kernel<<<dim3((N_NODES + 7) / 8, (F0 + 31) / 32), cb>>>(x, h, F0);
    gemm(h, W1, b1, y, N_NODES, F1, F0, 1);
    // layer 2: agg(y1) @ W2 + b2, relu
    agg_kernel<<<dim3((N_NODES + 7) / 8, (F1 + 31) / 32), cb>>>(y, h, F1);
    gemm(h, W2, b2, y, N_NODES, F2, F1, 1);
    // layer 3: agg(y2) @ W3 + b3, relu
    agg_kernel<<<dim3((N_NODES + 7) / 8, (F2 + 31) / 32), cb>>>(y, h, F2);
    gemm(h, W3, b3, y, N_NODES, F3, F2, 1);

    // segmented global max pool
    pool_kernel<<<dim3((N_GRAPHS + 7) / 8, (F3 + 31) / 32), cb>>>(y);

    // MLP head
    gemm(pool, Wg1, bg1, m1, N_GRAPHS, 1024, F3, 1);
    gemm(m1, Wg2, bg2, m2, N_GRAPHS, 128, 1024, 0);
    gemm(m2, Wf1, bf1, m1, N_GRAPHS, 1024, 128, 1);
    gemm(m1, Wf2, bf2, m2, N_GRAPHS, 512, 1024, 1);
    final_kernel<<<(N_GRAPHS + 7) / 8, cb>>>(m2, Wo, bo, out);
}

// round 4
// speedup vs baseline: 1.1677x; 1.0022x over previous
#include <cuda_runtime.h>
#include <cuda_bf16.h>
#include <math.h>
#include <stdint.h>

#define N_NODES  50000
#define N_EDGES  800000
#define N_GRAPHS 2048
#define NE_TOT   (N_EDGES + N_NODES)
#define F0 78
#define F1 78
#define F2 156
#define F3 312

// weight split-transpose offsets ([N][K] layout, bf16 hi/lo)
#define OW1  0
#define OW2  (OW1 + F1 * F0)          // 6084
#define OW3  (OW2 + F2 * F1)          // +12168
#define OWG1 (OW3 + F3 * F2)          // +48672
#define OWG2 (OWG1 + 1024 * F3)       // +319488
#define OWF1 (OWG2 + 128 * 1024)      // +131072
#define OWF2 (OWF1 + 1024 * 128)      // +131072
#define WTOT (OWF2 + 512 * 1024)      // +524288

// ---------------- scratch (device globals) ----------------
__device__ float    g_y[N_NODES * F3];          // layer output fp32 (agg gather input)
__device__ uint16_t g_ah[N_NODES * F3];         // split activations hi (GEMM A)
__device__ uint16_t g_al[N_NODES * F3];         // split activations lo
__device__ uint16_t g_wh[WTOT];                 // split weights hi, transposed [N][K]
__device__ uint16_t g_wl[WTOT];
__device__ uint16_t g_ph[N_GRAPHS * F3];        // pool split
__device__ uint16_t g_pl[N_GRAPHS * F3];
__device__ uint16_t g_m1h[N_GRAPHS * 1024], g_m1l[N_GRAPHS * 1024];
__device__ uint16_t g_m2h[N_GRAPHS * 1024], g_m2l[N_GRAPHS * 1024];
__device__ int   g_count[N_NODES];
__device__ float g_dinv[N_NODES];
__device__ int   g_rowptr[N_NODES + 1];
__device__ int   g_cursor[N_NODES];
__device__ int   g_csrc[NE_TOT];
__device__ float g_cw[NE_TOT];
__device__ int   g_src[N_EDGES];
__device__ int   g_dst[N_EDGES];
__device__ int   g_batch[N_NODES];
__device__ int   g_gstart[N_GRAPHS + 1];
__device__ int   g_is64;

__device__ __forceinline__ void fsplit(float v, uint16_t& hi, uint16_t& lo) {
    __nv_bfloat16 h = __float2bfloat16(v);
    __nv_bfloat16 l = __float2bfloat16(v - __bfloat162float(h));
    hi = __bfloat16_as_ushort(h);
    lo = __bfloat16_as_ushort(l);
}

// ---------------- dtype detection: int64 edge data has all odd 32-bit words == 0
__global__ void detect_kernel(const int* __restrict__ ei32) {
    __shared__ int sh[256];
    int t = threadIdx.x;
    int orv = 0;
    for (int i = t; i < 2048; i += 256) orv |= ei32[2 * i + 1];
    sh[t] = orv;
    __syncthreads();
    for (int o = 128; o; o >>= 1) {
        if (t < o) sh[t] |= sh[t + o];
        __syncthreads();
    }
    if (t == 0) g_is64 = (sh[0] == 0) ? 1 : 0;
}

__global__ void init_kernel() {
    int i = blockIdx.x * blockDim.x + threadIdx.x;
    if (i < N_NODES) g_count[i] = 1;  // self loop
}

// convert edges + degree histogram fused
__global__ void convert_edges_kernel(const void* __restrict__ ei) {
    int e = blockIdx.x * blockDim.x + threadIdx.x;
    if (e >= N_EDGES) return;
    int s, d;
    if (g_is64) {
        const long long* p = (const long long*)ei;
        s = (int)p[e];
        d = (int)p[N_EDGES + e];
    } else {
        const int* p = (const int*)ei;
        s = p[e];
        d = p[N_EDGES + e];
    }
    g_src[e] = s;
    g_dst[e] = d;
    atomicAdd(&g_count[d], 1);
}

__global__ void convert_batch_kernel(const void* __restrict__ b) {
    int i = blockIdx.x * blockDim.x + threadIdx.x;
    if (i >= N_NODES) return;
    g_batch[i] = g_is64 ? (int)((const long long*)b)[i] : ((const int*)b)[i];
}

__global__ void dinv_kernel() {
    int i = blockIdx.x * blockDim.x + threadIdx.x;
    if (i < N_NODES) g_dinv[i] = rsqrtf((float)g_count[i]);
}

__global__ void scan_kernel() {
    __shared__ int sums[1024];
    const int CH = (N_NODES + 1023) / 1024;
    int t = threadIdx.x;
    int base = t * CH;
    int s = 0;
    for (int i = 0; i < CH; i++) {
        int idx = base + i;
        if (idx < N_NODES) s += g_count[idx];
    }
    sums[t] = s;
    __syncthreads();
    for (int off = 1; off < 1024; off <<= 1) {
        int v = (t >= off) ? sums[t - off] : 0;
        __syncthreads();
        sums[t] += v;
        __syncthreads();
    }
    int run = (t == 0) ? 0 : sums[t - 1];
    for (int i = 0; i < CH; i++) {
        int idx = base + i;
        if (idx < N_NODES) {
            g_rowptr[idx] = run;
            g_cursor[idx] = run;
            run += g_count[idx];
        }
    }
    if (t == 1023) g_rowptr[N_NODES] = sums[1023];
}

__global__ void fill_edges_kernel() {
    int e = blockIdx.x * blockDim.x + threadIdx.x;
    if (e >= N_EDGES) return;
    int s = g_src[e];
    int d = g_dst[e];
    int p = atomicAdd(&g_cursor[d], 1);
    g_csrc[p] = s;
    g_cw[p] = g_dinv[s] * g_dinv[d];
}

__global__ void fill_self_kernel() {
    int i = blockIdx.x * blockDim.x + threadIdx.x;
    if (i >= N_NODES) return;
    int p = atomicAdd(&g_cursor[i], 1);
    g_csrc[p] = i;
    float di = g_dinv[i];
    g_cw[p] = di * di;
}

__global__ void gstart_kernel() {
    int i = blockIdx.x * blockDim.x + threadIdx.x;
    if (i > N_NODES) return;
    if (i == 0) {
        for (int g = 0; g <= g_batch[0]; g++) g_gstart[g] = 0;
    } else if (i == N_NODES) {
        for (int g = g_batch[N_NODES - 1] + 1; g <= N_GRAPHS; g++) g_gstart[g] = N_NODES;
    } else {
        int b0 = g_batch[i - 1], b1 = g_batch[i];
        for (int g = b0 + 1; g <= b1; g++) g_gstart[g] = i;
    }
}

// ---------------- weight split + transpose: W[K][N] fp32 -> wh/wl [N][K] bf16
__global__ void wsplit_kernel(const float* __restrict__ W, uint16_t* __restrict__ wh,
                              uint16_t* __restrict__ wl, int K, int N) {
    int idx = blockIdx.x * blockDim.x + threadIdx.x;
    if (idx >= K * N) return;
    int k = idx / N, n = idx % N;
    uint16_t h, l;
    fsplit(W[idx], h, l);
    wh[(size_t)n * K + k] = h;
    wl[(size_t)n * K + k] = l;
}

// ---------------- GCN aggregation: split(sum_e w_e * x[src_e]) ----------------
__global__ void agg_kernel(const float* __restrict__ x, uint16_t* __restrict__ ah,
                           uint16_t* __restrict__ al, int F)
{
    int node = blockIdx.x * blockDim.y + threadIdx.y;
    if (node >= N_NODES) return;
    int c = blockIdx.y * 32 + threadIdx.x;
    bool valid = c < F;
    int k0 = g_rowptr[node], k1 = g_rowptr[node + 1];
    float acc0 = 0.0f, acc1 = 0.0f;
    int k = k0;
    for (; k + 1 < k1; k += 2) {
        int sA = g_csrc[k], sB = g_csrc[k + 1];
        float wA = g_cw[k], wB = g_cw[k + 1];
        if (valid) {
            acc0 = fmaf(x[(size_t)sA * F + c], wA, acc0);
            acc1 = fmaf(x[(size_t)sB * F + c], wB, acc1);
        }
    }
    if (k < k1 && valid)
        acc0 = fmaf(x[(size_t)g_csrc[k] * F + c], g_cw[k], acc0);
    if (valid) {
        uint16_t h, l;
        fsplit(acc0 + acc1, h, l);
        ah[(size_t)node * F + c] = h;
        al[(size_t)node * F + c] = l;
    }
}

// ---------------- tensor-core GEMM, pre-split bf16 inputs ----------------
// C = act(A[M,K] @ B^T[N,K] + bias); A split hi/lo, B split hi/lo (transposed)
// out: mode 0 -> fp32 Cf; mode 1 -> split (Ch, Cl)
#define BM 128
#define BN 64

__device__ __forceinline__ void mma16816(float* c, const uint32_t* a, const uint32_t* b) {
    asm volatile(
        "mma.sync.aligned.m16n8k16.row.col.f32.bf16.bf16.f32 "
        "{%0,%1,%2,%3}, {%4,%5,%6,%7}, {%8,%9}, {%0,%1,%2,%3};\n"
        : "+f"(c[0]), "+f"(c[1]), "+f"(c[2]), "+f"(c[3])
        : "r"(a[0]), "r"(a[1]), "r"(a[2]), "r"(a[3]), "r"(b[0]), "r"(b[1]));
}

__global__ void __launch_bounds__(256) mma_gemm_kernel(
    const uint16_t* __restrict__ Ahp, const uint16_t* __restrict__ Alp,
    const uint16_t* __restrict__ Bhp, const uint16_t* __restrict__ Blp,
    const float* __restrict__ bias,
    float* __restrict__ Cf, uint16_t* __restrict__ Chp, uint16_t* __restrict__ Clp,
    int M, int N, int K, int relu)
{
    __shared__ uint32_t sAh[BM][9];   // [row][kpair]
    __shared__ uint32_t sAl[BM][9];
    __shared__ uint32_t sBh[BN][9];   // [n][kpair]
    __shared__ uint32_t sBl[BN][9];

    const uint32_t* Ah32 = (const uint32_t*)Ahp;
    const uint32_t* Al32 = (const uint32_t*)Alp;
    const uint32_t* Bh32 = (const uint32_t*)Bhp;
    const uint32_t* Bl32 = (const uint32_t*)Blp;
    int K2 = K >> 1;

    int tid = threadIdx.x;
    int warp = tid >> 5, lane = tid & 31;
    int wm = warp >> 1;
    int wn = warp & 1;
    int g = lane >> 2, tg = lane & 3;
    int rowBase = blockIdx.y * BM;
    int colBase = blockIdx.x * BN;

    float acc[2][4][4];
    #pragma unroll
    for (int mt = 0; mt < 2; mt++)
        #pragma unroll
        for (int nt = 0; nt < 4; nt++)
            #pragma unroll
            for (int i = 0; i < 4; i++) acc[mt][nt][i] = 0.0f;

    int rowA = tid >> 1;              // 0..127
    int kpA = (tid & 1) * 4;          // kpair base within tile: 0 or 4
    int nB = tid & 63;                // 0..63
    int kpB = tid >> 6;               // 0..3 (also +4)

    for (int k0 = 0; k0 < K; k0 += 16) {
        int kp0 = k0 >> 1;
        __syncthreads();
        // A tile: 128 rows x 8 kpairs
        {
            int gr = rowBase + rowA;
            bool rok = gr < M;
            size_t base = (size_t)gr * K2;
            #pragma unroll
            for (int p = 0; p < 4; p++) {
                int kp = kp0 + kpA + p;
                bool ok = rok && kp < K2;
                sAh[rowA][kpA + p] = ok ? Ah32[base + kp] : 0u;
                sAl[rowA][kpA + p] = ok ? Al32[base + kp] : 0u;
            }
        }
        // B tile: 64 n x 8 kpairs
        {
            int gc = colBase + nB;
            bool cok = gc < N;
            size_t base = (size_t)gc * K2;
            #pragma unroll
            for (int p = 0; p < 2; p++) {
                int kpi = kpB + p * 4;
                int kp = kp0 + kpi;
                bool ok = cok && kp < K2;
                sBh[nB][kpi] = ok ? Bh32[base + kp] : 0u;
                sBl[nB][kpi] = ok ? Bl32[base + kp] : 0u;
            }
        }
        __syncthreads();

        uint32_t af[2][2][4];
        #pragma unroll
        for (int mt = 0; mt < 2; mt++) {
            int r0 = wm * 32 + mt * 16 + g;
            af[0][mt][0] = sAh[r0][tg];     af[0][mt][1] = sAh[r0 + 8][tg];
            af[0][mt][2] = sAh[r0][tg + 4]; af[0][mt][3] = sAh[r0 + 8][tg + 4];
            af[1][mt][0] = sAl[r0][tg];     af[1][mt][1] = sAl[r0 + 8][tg];
            af[1][mt][2] = sAl[r0][tg + 4]; af[1][mt][3] = sAl[r0 + 8][tg + 4];
        }
        uint32_t bfr[2][4][2];
        #pragma unroll
        for (int nt = 0; nt < 4; nt++) {
            int n0 = wn * 32 + nt * 8 + g;
            bfr[0][nt][0] = sBh[n0][tg]; bfr[0][nt][1] = sBh[n0][tg + 4];
            bfr[1][nt][0] = sBl[n0][tg]; bfr[1][nt][1] = sBl[n0][tg + 4];
        }
        #pragma unroll
        for (int mt = 0; mt < 2; mt++)
            #pragma unroll
            for (int nt = 0; nt < 4; nt++) {
                mma16816(acc[mt][nt], af[0][mt], bfr[0][nt]);  // hi*hi
                mma16816(acc[mt][nt], af[0][mt], bfr[1][nt]);  // hi*lo
                mma16816(acc[mt][nt], af[1][mt], bfr[0][nt]);  // lo*hi
            }
    }

    // epilogue
    #pragma unroll
    for (int mt = 0; mt < 2; mt++) {
        int r0 = rowBase + wm * 32 + mt * 16 + g;
        #pragma unroll
        for (int nt = 0; nt < 4; nt++) {
            int c0 = colBase + wn * 32 + nt * 8 + tg * 2;
            #pragma unroll
            for (int half = 0; half < 2; half++) {
                int r = r0 + half * 8;
                if (r >= M || c0 >= N) continue;
                float v0 = acc[mt][nt][half * 2 + 0];
                float v1 = acc[mt][nt][half * 2 + 1];
                v0 += bias[c0];
                v1 += bias[c0 + 1];
                if (relu) { v0 = fmaxf(v0, 0.0f); v1 = fmaxf(v1, 0.0f); }
                if (Cf) {
                    Cf[(size_t)r * N + c0]     = v0;
                    Cf[(size_t)r * N + c0 + 1] = v1;
                } else {
                    uint16_t h0, l0, h1, l1;
                    fsplit(v0, h0, l0);
                    fsplit(v1, h1, l1);
                    ((uint32_t*)Chp)[((size_t)r * N + c0) >> 1] = ((uint32_t)h1 << 16) | h0;
                    ((uint32_t*)Clp)[((size_t)r * N + c0) >> 1] = ((uint32_t)l1 << 16) | l0;
                }
            }
        }
    }
}

// ---------------- segmented global max pool -> split ----------------
__global__ void pool_kernel(const float* __restrict__ y)
{
    int grp = blockIdx.x * blockDim.y + threadIdx.y;
    if (grp >= N_GRAPHS) return;
    int c = blockIdx.y * 32 + threadIdx.x;
    if (c >= F3) return;
    int s = g_gstart[grp], e = g_gstart[grp + 1];
    float m = 0.0f;  // relu outputs >= 0
    for (int i = s; i < e; i++) m = fmaxf(m, y[(size_t)i * F3 + c]);
    uint16_t h, l;
    fsplit(m, h, l);
    g_ph[(size_t)grp * F3 + c] = h;
    g_pl[(size_t)grp * F3 + c] = l;
}

// ---------------- final 512 -> 1 dot + sigmoid (split input) ----------------
__global__ void final_kernel(const float* __restrict__ Wo,
                             const float* __restrict__ bo, float* __restrict__ out)
{
    int row = blockIdx.x * blockDim.y + threadIdx.y;
    if (row >= N_GRAPHS) return;
    int lane = threadIdx.x;
    float s = 0.0f;
    for (int k = lane; k < 512; k += 32) {
        float v = __bfloat162float(__ushort_as_bfloat16(g_m2h[(size_t)row * 512 + k]))
                + __bfloat162float(__ushort_as_bfloat16(g_m2l[(size_t)row * 512 + k]));
        s = fmaf(v, Wo[k], s);
    }
    #pragma unroll
    for (int o = 16; o; o >>= 1) s += __shfl_xor_sync(0xFFFFFFFFu, s, o);
    if (lane == 0) out[row] = 1.0f / (1.0f + expf(-(s + bo[0])));
}

// ---------------- launch ----------------
extern "C" void kernel_launch(void* const* d_in, const int* in_sizes, int n_in,
                              void* d_out, int out_size)
{
    const float* x     = (const float*)d_in[0];
    const void*  ei    = d_in[1];
    const void*  batch = d_in[2];
    const float* W1 = (const float*)d_in[3];  const float* b1 = (const float*)d_in[4];
    const float* W2 = (const float*)d_in[5];  const float* b2 = (const float*)d_in[6];
    const float* W3 = (const float*)d_in[7];  const float* b3 = (const float*)d_in[8];
    const float* Wg1 = (const float*)d_in[9];  const float* bg1 = (const float*)d_in[10];
    const float* Wg2 = (const float*)d_in[11]; const float* bg2 = (const float*)d_in[12];
    const float* Wf1 = (const float*)d_in[13]; const float* bf1 = (const float*)d_in[14];
    const float* Wf2 = (const float*)d_in[15]; const float* bf2 = (const float*)d_in[16];
    const float* Wo  = (const float*)d_in[17]; const float* bo  = (const float*)d_in[18];
    float* out = (float*)d_out;

    float *y;
    uint16_t *ah, *al, *wh, *wl, *ph, *pl, *m1h, *m1l, *m2h, *m2l;
    cudaGetSymbolAddress((void**)&y,   g_y);
    cudaGetSymbolAddress((void**)&ah,  g_ah);
    cudaGetSymbolAddress((void**)&al,  g_al);
    cudaGetSymbolAddress((void**)&wh,  g_wh);
    cudaGetSymbolAddress((void**)&wl,  g_wl);
    cudaGetSymbolAddress((void**)&ph,  g_ph);
    cudaGetSymbolAddress((void**)&pl,  g_pl);
    cudaGetSymbolAddress((void**)&m1h, g_m1h);
    cudaGetSymbolAddress((void**)&m1l, g_m1l);
    cudaGetSymbolAddress((void**)&m2h, g_m2h);
    cudaGetSymbolAddress((void**)&m2l, g_m2l);

    // dtype detect + preprocessing
    detect_kernel<<<1, 256>>>((const int*)ei);
    init_kernel<<<(N_NODES + 255) / 256, 256>>>();
    convert_edges_kernel<<<(N_EDGES + 255) / 256, 256>>>(ei);
    convert_batch_kernel<<<(N_NODES + 255) / 256, 256>>>(batch);
    dinv_kernel<<<(N_NODES + 255) / 256, 256>>>();
    scan_kernel<<<1, 1024>>>();
    fill_edges_kernel<<<(N_EDGES + 255) / 256, 256>>>();
    fill_self_kernel<<<(N_NODES + 255) / 256, 256>>>();
    gstart_kernel<<<(N_NODES + 256) / 256, 256>>>();

    // weight split+transpose
    auto wsp = [&](const float* W, int off, int K, int N) {
        wsplit_kernel<<<(K * N + 255) / 256, 256>>>(W, wh + off, wl + off, K, N);
    };
    wsp(W1, OW1, F0, F1);
    wsp(W2, OW2, F1, F2);
    wsp(W3, OW3, F2, F3);
    wsp(Wg1, OWG1, F3, 1024);
    wsp(Wg2, OWG2, 1024, 128);
    wsp(Wf1, OWF1, 128, 1024);
    wsp(Wf2, OWF2, 1024, 512);

    auto gemm = [&](const uint16_t* Ah, const uint16_t* Al, int woff,
                    const float* bias, float* Cf, uint16_t* Ch, uint16_t* Cl,
                    int M, int N, int K, int relu) {
        dim3 grid((N + BN - 1) / BN, (M + BM - 1) / BM);
        mma_gemm_kernel<<<grid, 256>>>(Ah, Al, wh + woff, wl + woff, bias,
                                       Cf, Ch, Cl, M, N, K, relu);
    };
    dim3 cb(32, 8);

    // layer 1
    agg_kernel<<<dim3((N_NODES + 7) / 8, (F0 + 31) / 32), cb>>>(x, ah, al, F0);
    gemm(ah, al, OW1, b1, y, nullptr, nullptr, N_NODES, F1, F0, 1);
    // layer 2
    agg_kernel<<<dim3((N_NODES + 7) / 8, (F1 + 31) / 32), cb>>>(y, ah, al, F1);
    gemm(ah, al, OW2, b2, y, nullptr, nullptr, N_NODES, F2, F1, 1);
    // layer 3
    agg_kernel<<<dim3((N_NODES + 7) / 8, (F2 + 31) / 32), cb>>>(y, ah, al, F2);
    gemm(ah, al, OW3, b3, y, nullptr, nullptr, N_NODES, F3, F2, 1);

    // pool -> split
    pool_kernel<<<dim3((N_GRAPHS + 7) / 8, (F3 + 31) / 32), cb>>>(y);

    // MLP head (split all the way)
    gemm(ph, pl,  OWG1, bg1, nullptr, m1h, m1l, N_GRAPHS, 1024, F3,  1);
    gemm(m1h, m1l, OWG2, bg2, nullptr, m2h, m2l, N_GRAPHS, 128, 1024, 0);
    gemm(m2h, m2l, OWF1, bf1, nullptr, m1h, m1l, N_GRAPHS, 1024, 128, 1);
    gemm(m1h, m1l, OWF2, bf2, nullptr, m2h, m2l, N_GRAPHS, 512, 1024, 1);
    final_kernel<<<(N_GRAPHS + 7) / 8, cb>>>(Wo, bo, out);
}

// round 5
// speedup vs baseline: 1.3600x; 1.1647x over previous
#include <cuda_runtime.h>
#include <cuda_bf16.h>
#include <math.h>
#include <stdint.h>

#define N_NODES  50000
#define N_EDGES  800000
#define N_GRAPHS 2048
#define NE_TOT   (N_EDGES + N_NODES)
#define F0 78
#define F1 78
#define F2 156
#define F3 312

// weight split-transpose offsets ([N][K] layout, bf16 hi/lo)
#define OW1  0
#define OW2  (OW1 + F1 * F0)
#define OW3  (OW2 + F2 * F1)
#define OWG1 (OW3 + F3 * F2)
#define OWG2 (OWG1 + 1024 * F3)
#define OWF1 (OWG2 + 128 * 1024)
#define OWF2 (OWF1 + 1024 * 128)
#define WTOT (OWF2 + 512 * 1024)

#define SEG_EDGE  N_EDGES
#define SEG_BATCH (SEG_EDGE + N_NODES)
#define NW1  (F0 * F1)
#define NW2  (F1 * F2)
#define NW3  (F2 * F3)
#define NWG1 (F3 * 1024)
#define NWG2 (1024 * 128)
#define NWF1 (128 * 1024)
#define NWF2 (1024 * 512)
#define SEG_W1  (SEG_BATCH + NW1)
#define SEG_W2  (SEG_W1 + NW2)
#define SEG_W3  (SEG_W2 + NW3)
#define SEG_WG1 (SEG_W3 + NWG1)
#define SEG_WG2 (SEG_WG1 + NWG2)
#define SEG_WF1 (SEG_WG2 + NWF1)
#define SEG_WF2 (SEG_WF1 + NWF2)
#define PREP_TOT SEG_WF2

struct EdgeRec { int src; float w; };

// ---------------- scratch (device globals) ----------------
__device__ float    g_y[N_NODES * F3];
__device__ uint16_t g_ah[N_NODES * F3];
__device__ uint16_t g_al[N_NODES * F3];
__device__ uint16_t g_wh[WTOT];
__device__ uint16_t g_wl[WTOT];
__device__ uint16_t g_ph[N_GRAPHS * F3];
__device__ uint16_t g_pl[N_GRAPHS * F3];
__device__ uint16_t g_m1h[N_GRAPHS * 1024], g_m1l[N_GRAPHS * 1024];
__device__ uint16_t g_m2h[N_GRAPHS * 1024], g_m2l[N_GRAPHS * 1024];
__device__ int     g_count[N_NODES];     // zero at load; scan resets to zero each launch
__device__ float   g_dinv[N_NODES];
__device__ int     g_rowptr[N_NODES + 1];
__device__ int     g_cursor[N_NODES];
__device__ EdgeRec g_edge[NE_TOT];
__device__ int     g_src[N_EDGES];
__device__ int     g_dst[N_EDGES];
__device__ int     g_batch[N_NODES];
__device__ int     g_gstart[N_GRAPHS + 1];
__device__ int     g_is64;

__device__ __forceinline__ void fsplit(float v, uint16_t& hi, uint16_t& lo) {
    __nv_bfloat16 h = __float2bfloat16(v);
    __nv_bfloat16 l = __float2bfloat16(v - __bfloat162float(h));
    hi = __bfloat16_as_ushort(h);
    lo = __bfloat16_as_ushort(l);
}

// ---------------- dtype detection ----------------
__global__ void detect_kernel(const int* __restrict__ ei32) {
    __shared__ int sh[256];
    int t = threadIdx.x;
    int orv = 0;
    for (int i = t; i < 2048; i += 256) orv |= ei32[2 * i + 1];
    sh[t] = orv;
    __syncthreads();
    for (int o = 128; o; o >>= 1) {
        if (t < o) sh[t] |= sh[t + o];
        __syncthreads();
    }
    if (t == 0) g_is64 = (sh[0] == 0) ? 1 : 0;
}

// ---------------- fused prep: edges+hist, batch, all weight splits ----------------
__device__ __forceinline__ void wsplit_one(const float* W, int off, int K, int N, int idx) {
    int k = idx / N, n = idx % N;
    uint16_t h, l;
    fsplit(W[idx], h, l);
    g_wh[(size_t)off + (size_t)n * K + k] = h;
    g_wl[(size_t)off + (size_t)n * K + k] = l;
}

__global__ void prep_kernel(const void* __restrict__ ei, const void* __restrict__ batch,
                            const float* __restrict__ W1, const float* __restrict__ W2,
                            const float* __restrict__ W3, const float* __restrict__ Wg1,
                            const float* __restrict__ Wg2, const float* __restrict__ Wf1,
                            const float* __restrict__ Wf2)
{
    int idx = blockIdx.x * blockDim.x + threadIdx.x;
    if (idx >= PREP_TOT) return;
    if (idx < SEG_EDGE) {
        int e = idx, s, d;
        if (g_is64) {
            const long long* p = (const long long*)ei;
            s = (int)p[e];
            d = (int)p[N_EDGES + e];
        } else {
            const int* p = (const int*)ei;
            s = p[e];
            d = p[N_EDGES + e];
        }
        g_src[e] = s;
        g_dst[e] = d;
        atomicAdd(&g_count[d], 1);
    } else if (idx < SEG_BATCH) {
        int i = idx - SEG_EDGE;
        g_batch[i] = g_is64 ? (int)((const long long*)batch)[i] : ((const int*)batch)[i];
    } else if (idx < SEG_W1)  wsplit_one(W1,  OW1,  F0,   F1,   idx - SEG_BATCH);
    else if (idx < SEG_W2)    wsplit_one(W2,  OW2,  F1,   F2,   idx - SEG_W1);
    else if (idx < SEG_W3)    wsplit_one(W3,  OW3,  F2,   F3,   idx - SEG_W2);
    else if (idx < SEG_WG1)   wsplit_one(Wg1, OWG1, F3,   1024, idx - SEG_W3);
    else if (idx < SEG_WG2)   wsplit_one(Wg2, OWG2, 1024, 128,  idx - SEG_WG1);
    else if (idx < SEG_WF1)   wsplit_one(Wf1, OWF1, 128,  1024, idx - SEG_WG2);
    else                      wsplit_one(Wf2, OWF2, 1024, 512,  idx - SEG_WF1);
}

// deg = count+1 (self loop); count reset happens in scan
__global__ void dinv_kernel() {
    int i = blockIdx.x * blockDim.x + threadIdx.x;
    if (i < N_NODES) g_dinv[i] = rsqrtf((float)(g_count[i] + 1));
}

// single-block exclusive scan over (count+1); resets count for next replay
__global__ void scan_kernel() {
    __shared__ int sums[1024];
    const int CH = (N_NODES + 1023) / 1024;
    int t = threadIdx.x;
    int base = t * CH;
    int s = 0;
    for (int i = 0; i < CH; i++) {
        int idx = base + i;
        if (idx < N_NODES) s += g_count[idx] + 1;
    }
    sums[t] = s;
    __syncthreads();
    for (int off = 1; off < 1024; off <<= 1) {
        int v = (t >= off) ? sums[t - off] : 0;
        __syncthreads();
        sums[t] += v;
        __syncthreads();
    }
    int run = (t == 0) ? 0 : sums[t - 1];
    for (int i = 0; i < CH; i++) {
        int idx = base + i;
        if (idx < N_NODES) {
            int d = g_count[idx] + 1;
            g_count[idx] = 0;          // reset for next graph replay
            g_rowptr[idx] = run;
            g_cursor[idx] = run;
            run += d;
        }
    }
    if (t == 1023) g_rowptr[N_NODES] = sums[1023];
}

// fused: edges + self loops into packed EdgeRec CSR
__global__ void fill_kernel() {
    int t = blockIdx.x * blockDim.x + threadIdx.x;
    if (t >= NE_TOT) return;
    if (t < N_EDGES) {
        int s = g_src[t];
        int d = g_dst[t];
        int p = atomicAdd(&g_cursor[d], 1);
        EdgeRec r;
        r.src = s;
        r.w = g_dinv[s] * g_dinv[d];
        g_edge[p] = r;
    } else {
        int i = t - N_EDGES;
        int p = atomicAdd(&g_cursor[i], 1);
        float di = g_dinv[i];
        EdgeRec r;
        r.src = i;
        r.w = di * di;
        g_edge[p] = r;
    }
}

__global__ void gstart_kernel() {
    int i = blockIdx.x * blockDim.x + threadIdx.x;
    if (i > N_NODES) return;
    if (i == 0) {
        for (int g = 0; g <= g_batch[0]; g++) g_gstart[g] = 0;
    } else if (i == N_NODES) {
        for (int g = g_batch[N_NODES - 1] + 1; g <= N_GRAPHS; g++) g_gstart[g] = N_NODES;
    } else {
        int b0 = g_batch[i - 1], b1 = g_batch[i];
        for (int g = b0 + 1; g <= b1; g++) g_gstart[g] = i;
    }
}

// ---------------- GCN aggregation: warp per node, all F cols in registers ----------------
template <int CH>
__global__ void __launch_bounds__(256) agg_kernel_t(
    const float* __restrict__ x, uint16_t* __restrict__ ah,
    uint16_t* __restrict__ al, int F)
{
    int node = blockIdx.x * 8 + threadIdx.y;
    if (node >= N_NODES) return;
    int lane = threadIdx.x;
    int k0 = g_rowptr[node], k1 = g_rowptr[node + 1];
    float acc[CH];
    #pragma unroll
    for (int i = 0; i < CH; i++) acc[i] = 0.0f;

    const int2* ep = (const int2*)g_edge;
    #pragma unroll 2
    for (int k = k0; k < k1; k++) {
        int2 er = ep[k];                       // one 8B broadcast load per edge
        int src = er.x;
        float w = __int_as_float(er.y);
        const float* row = x + (size_t)src * F;
        #pragma unroll
        for (int i = 0; i < CH; i++) {
            int c = i * 32 + lane;
            float v = (c < F) ? row[c] : 0.0f;
            acc[i] = fmaf(v, w, acc[i]);
        }
    }
    #pragma unroll
    for (int i = 0; i < CH; i++) {
        int c = i * 32 + lane;
        if (c < F) {
            uint16_t h, l;
            fsplit(acc[i], h, l);
            ah[(size_t)node * F + c] = h;
            al[(size_t)node * F + c] = l;
        }
    }
}

// ---------------- tensor-core GEMM, pre-split bf16 inputs ----------------
#define BM 128
#define BN 64

__device__ __forceinline__ void mma16816(float* c, const uint32_t* a, const uint32_t* b) {
    asm volatile(
        "mma.sync.aligned.m16n8k16.row.col.f32.bf16.bf16.f32 "
        "{%0,%1,%2,%3}, {%4,%5,%6,%7}, {%8,%9}, {%0,%1,%2,%3};\n"
        : "+f"(c[0]), "+f"(c[1]), "+f"(c[2]), "+f"(c[3])
        : "r"(a[0]), "r"(a[1]), "r"(a[2]), "r"(a[3]), "r"(b[0]), "r"(b[1]));
}

__global__ void __launch_bounds__(256) mma_gemm_kernel(
    const uint16_t* __restrict__ Ahp, const uint16_t* __restrict__ Alp,
    const uint16_t* __restrict__ Bhp, const uint16_t* __restrict__ Blp,
    const float* __restrict__ bias,
    float* __restrict__ Cf, uint16_t* __restrict__ Chp, uint16_t* __restrict__ Clp,
    int M, int N, int K, int relu)
{
    __shared__ uint32_t sAh[BM][9];
    __shared__ uint32_t sAl[BM][9];
    __shared__ uint32_t sBh[BN][9];
    __shared__ uint32_t sBl[BN][9];

    const uint32_t* Ah32 = (const uint32_t*)Ahp;
    const uint32_t* Al32 = (const uint32_t*)Alp;
    const uint32_t* Bh32 = (const uint32_t*)Bhp;
    const uint32_t* Bl32 = (const uint32_t*)Blp;
    int K2 = K >> 1;

    int tid = threadIdx.x;
    int warp = tid >> 5, lane = tid & 31;
    int wm = warp >> 1;
    int wn = warp & 1;
    int g = lane >> 2, tg = lane & 3;
    int rowBase = blockIdx.y * BM;
    int colBase = blockIdx.x * BN;

    float acc[2][4][4];
    #pragma unroll
    for (int mt = 0; mt < 2; mt++)
        #pragma unroll
        for (int nt = 0; nt < 4; nt++)
            #pragma unroll
            for (int i = 0; i < 4; i++) acc[mt][nt][i] = 0.0f;

    int rowA = tid >> 1;
    int kpA = (tid & 1) * 4;
    int nB = tid & 63;
    int kpB = tid >> 6;

    for (int k0 = 0; k0 < K; k0 += 16) {
        int kp0 = k0 >> 1;
        __syncthreads();
        {
            int gr = rowBase + rowA;
            bool rok = gr < M;
            size_t base = (size_t)gr * K2;
            #pragma unroll
            for (int p = 0; p < 4; p++) {
                int kp = kp0 + kpA + p;
                bool ok = rok && kp < K2;
                sAh[rowA][kpA + p] = ok ? Ah32[base + kp] : 0u;
                sAl[rowA][kpA + p] = ok ? Al32[base + kp] : 0u;
            }
        }
        {
            int gc = colBase + nB;
            bool cok = gc < N;
            size_t base = (size_t)gc * K2;
            #pragma unroll
            for (int p = 0; p < 2; p++) {
                int kpi = kpB + p * 4;
                int kp = kp0 + kpi;
                bool ok = cok && kp < K2;
                sBh[nB][kpi] = ok ? Bh32[base + kp] : 0u;
                sBl[nB][kpi] = ok ? Bl32[base + kp] : 0u;
            }
        }
        __syncthreads();

        uint32_t af[2][2][4];
        #pragma unroll
        for (int mt = 0; mt < 2; mt++) {
            int r0 = wm * 32 + mt * 16 + g;
            af[0][mt][0] = sAh[r0][tg];     af[0][mt][1] = sAh[r0 + 8][tg];
            af[0][mt][2] = sAh[r0][tg + 4]; af[0][mt][3] = sAh[r0 + 8][tg + 4];
            af[1][mt][0] = sAl[r0][tg];     af[1][mt][1] = sAl[r0 + 8][tg];
            af[1][mt][2] = sAl[r0][tg + 4]; af[1][mt][3] = sAl[r0 + 8][tg + 4];
        }
        uint32_t bfr[2][4][2];
        #pragma unroll
        for (int nt = 0; nt < 4; nt++) {
            int n0 = wn * 32 + nt * 8 + g;
            bfr[0][nt][0] = sBh[n0][tg]; bfr[0][nt][1] = sBh[n0][tg + 4];
            bfr[1][nt][0] = sBl[n0][tg]; bfr[1][nt][1] = sBl[n0][tg + 4];
        }
        #pragma unroll
        for (int mt = 0; mt < 2; mt++)
            #pragma unroll
            for (int nt = 0; nt < 4; nt++) {
                mma16816(acc[mt][nt], af[0][mt], bfr[0][nt]);
                mma16816(acc[mt][nt], af[0][mt], bfr[1][nt]);
                mma16816(acc[mt][nt], af[1][mt], bfr[0][nt]);
            }
    }

    #pragma unroll
    for (int mt = 0; mt < 2; mt++) {
        int r0 = rowBase + wm * 32 + mt * 16 + g;
        #pragma unroll
        for (int nt = 0; nt < 4; nt++) {
            int c0 = colBase + wn * 32 + nt * 8 + tg * 2;
            #pragma unroll
            for (int half = 0; half < 2; half++) {
                int r = r0 + half * 8;
                if (r >= M || c0 >= N) continue;
                float v0 = acc[mt][nt][half * 2 + 0];
                float v1 = acc[mt][nt][half * 2 + 1];
                v0 += bias[c0];
                v1 += bias[c0 + 1];
                if (relu) { v0 = fmaxf(v0, 0.0f); v1 = fmaxf(v1, 0.0f); }
                if (Cf) {
                    Cf[(size_t)r * N + c0]     = v0;
                    Cf[(size_t)r * N + c0 + 1] = v1;
                } else {
                    uint16_t h0, l0, h1, l1;
                    fsplit(v0, h0, l0);
                    fsplit(v1, h1, l1);
                    ((uint32_t*)Chp)[((size_t)r * N + c0) >> 1] = ((uint32_t)h1 << 16) | h0;
                    ((uint32_t*)Clp)[((size_t)r * N + c0) >> 1] = ((uint32_t)l1 << 16) | l0;
                }
            }
        }
    }
}

// ---------------- segmented global max pool -> split ----------------
__global__ void pool_kernel(const float* __restrict__ y)
{
    int grp = blockIdx.x * blockDim.y + threadIdx.y;
    if (grp >= N_GRAPHS) return;
    int c = blockIdx.y * 32 + threadIdx.x;
    if (c >= F3) return;
    int s = g_gstart[grp], e = g_gstart[grp + 1];
    float m = 0.0f;
    for (int i = s; i < e; i++) m = fmaxf(m, y[(size_t)i * F3 + c]);
    uint16_t h, l;
    fsplit(m, h, l);
    g_ph[(size_t)grp * F3 + c] = h;
    g_pl[(size_t)grp * F3 + c] = l;
}

// ---------------- final 512 -> 1 dot + sigmoid ----------------
__global__ void final_kernel(const float* __restrict__ Wo,
                             const float* __restrict__ bo, float* __restrict__ out)
{
    int row = blockIdx.x * blockDim.y + threadIdx.y;
    if (row >= N_GRAPHS) return;
    int lane = threadIdx.x;
    float s = 0.0f;
    for (int k = lane; k < 512; k += 32) {
        float v = __bfloat162float(__ushort_as_bfloat16(g_m2h[(size_t)row * 512 + k]))
                + __bfloat162float(__ushort_as_bfloat16(g_m2l[(size_t)row * 512 + k]));
        s = fmaf(v, Wo[k], s);
    }
    #pragma unroll
    for (int o = 16; o; o >>= 1) s += __shfl_xor_sync(0xFFFFFFFFu, s, o);
    if (lane == 0) out[row] = 1.0f / (1.0f + expf(-(s + bo[0])));
}

// ---------------- launch ----------------
extern "C" void kernel_launch(void* const* d_in, const int* in_sizes, int n_in,
                              void* d_out, int out_size)
{
    const float* x     = (const float*)d_in[0];
    const void*  ei    = d_in[1];
    const void*  batch = d_in[2];
    const float* W1 = (const float*)d_in[3];  const float* b1 = (const float*)d_in[4];
    const float* W2 = (const float*)d_in[5];  const float* b2 = (const float*)d_in[6];
    const float* W3 = (const float*)d_in[7];  const float* b3 = (const float*)d_in[8];
    const float* Wg1 = (const float*)d_in[9];  const float* bg1 = (const float*)d_in[10];
    const float* Wg2 = (const float*)d_in[11]; const float* bg2 = (const float*)d_in[12];
    const float* Wf1 = (const float*)d_in[13]; const float* bf1 = (const float*)d_in[14];
    const float* Wf2 = (const float*)d_in[15]; const float* bf2 = (const float*)d_in[16];
    const float* Wo  = (const float*)d_in[17]; const float* bo  = (const float*)d_in[18];
    float* out = (float*)d_out;

    float *y;
    uint16_t *ah, *al, *wh, *wl, *ph, *pl, *m1h, *m1l, *m2h, *m2l;
    cudaGetSymbolAddress((void**)&y,   g_y);
    cudaGetSymbolAddress((void**)&ah,  g_ah);
    cudaGetSymbolAddress((void**)&al,  g_al);
    cudaGetSymbolAddress((void**)&wh,  g_wh);
    cudaGetSymbolAddress((void**)&wl,  g_wl);
    cudaGetSymbolAddress((void**)&ph,  g_ph);
    cudaGetSymbolAddress((void**)&pl,  g_pl);
    cudaGetSymbolAddress((void**)&m1h, g_m1h);
    cudaGetSymbolAddress((void**)&m1l, g_m1l);
    cudaGetSymbolAddress((void**)&m2h, g_m2h);
    cudaGetSymbolAddress((void**)&m2l, g_m2l);

    // preprocessing: 5 launches
    detect_kernel<<<1, 256>>>((const int*)ei);
    prep_kernel<<<(PREP_TOT + 255) / 256, 256>>>(ei, batch, W1, W2, W3, Wg1, Wg2, Wf1, Wf2);
    dinv_kernel<<<(N_NODES + 255) / 256, 256>>>();
    scan_kernel<<<1, 1024>>>();
    fill_kernel<<<(NE_TOT + 255) / 256, 256>>>();

    auto gemm = [&](const uint16_t* Ah, const uint16_t* Al, int woff,
                    const float* bias, float* Cf, uint16_t* Ch, uint16_t* Cl,
                    int M, int N, int K, int relu) {
        dim3 grid((N + BN - 1) / BN, (M + BM - 1) / BM);
        mma_gemm_kernel<<<grid, 256>>>(Ah, Al, wh + woff, wl + woff, bias,
                                       Cf, Ch, Cl, M, N, K, relu);
    };
    dim3 cb(32, 8);

    // layer 1 (agg over F0=78 -> 3 chunks)
    agg_kernel_t<3><<<(N_NODES + 7) / 8, cb>>>(x, ah, al, F0);
    gemm(ah, al, OW1, b1, y, nullptr, nullptr, N_NODES, F1, F0, 1);
    // layer 2 (F1=78 -> 3 chunks)
    agg_kernel_t<3><<<(N_NODES + 7) / 8, cb>>>(y, ah, al, F1);
    gemm(ah, al, OW2, b2, y, nullptr, nullptr, N_NODES, F2, F1, 1);
    // layer 3 (F2=156 -> 5 chunks)
    agg_kernel_t<5><<<(N_NODES + 7) / 8, cb>>>(y, ah, al, F2);
    gemm(ah, al, OW3, b3, y, nullptr, nullptr, N_NODES, F3, F2, 1);

    // pool
    gstart_kernel<<<(N_NODES + 256) / 256, 256>>>();
    pool_kernel<<<dim3((N_GRAPHS + 7) / 8, (F3 + 31) / 32), cb>>>(y);

    // MLP head
    gemm(ph, pl,   OWG1, bg1, nullptr, m1h, m1l, N_GRAPHS, 1024, F3,  1);
    gemm(m1h, m1l, OWG2, bg2, nullptr, m2h, m2l, N_GRAPHS, 128, 1024, 0);
    gemm(m2h, m2l, OWF1, bf1, nullptr, m1h, m1l, N_GRAPHS, 1024, 128, 1);
    gemm(m1h, m1l, OWF2, bf2, nullptr, m2h, m2l, N_GRAPHS, 512, 1024, 1);
    final_kernel<<<(N_GRAPHS + 7) / 8, cb>>>(Wo, bo, out);
}

// round 6
// speedup vs baseline: 1.5522x; 1.1414x over previous
#include <cuda_runtime.h>
#include <cuda_bf16.h>
#include <math.h>
#include <stdint.h>

#define N_NODES  50000
#define N_EDGES  800000
#define N_GRAPHS 2048
#define NE_TOT   (N_EDGES + N_NODES)
#define F0 78
#define F1 78
#define F2 156
#define F3 312

#define SCAN_NB ((N_NODES + 255) / 256)   // 196

// weight split-transpose offsets ([N][K] layout, bf16 hi/lo)
#define OW1  0
#define OW2  (OW1 + F1 * F0)
#define OW3  (OW2 + F2 * F1)
#define OWG1 (OW3 + F3 * F2)
#define OWG2 (OWG1 + 1024 * F3)
#define OWF1 (OWG2 + 128 * 1024)
#define OWF2 (OWF1 + 1024 * 128)
#define WTOT (OWF2 + 512 * 1024)

#define SEG_EDGE  N_EDGES
#define SEG_BATCH (SEG_EDGE + N_NODES)
#define NW1  (F0 * F1)
#define NW2  (F1 * F2)
#define NW3  (F2 * F3)
#define NWG1 (F3 * 1024)
#define NWG2 (1024 * 128)
#define NWF1 (128 * 1024)
#define NWF2 (1024 * 512)
#define SEG_W1  (SEG_BATCH + NW1)
#define SEG_W2  (SEG_W1 + NW2)
#define SEG_W3  (SEG_W2 + NW3)
#define SEG_WG1 (SEG_W3 + NWG1)
#define SEG_WG2 (SEG_WG1 + NWG2)
#define SEG_WF1 (SEG_WG2 + NWF1)
#define SEG_WF2 (SEG_WF1 + NWF2)
#define PREP_TOT SEG_WF2

struct EdgeRec { int src; float w; };

// ---------------- scratch (device globals) ----------------
__device__ float    g_y[N_NODES * F3];
__device__ uint16_t g_ah[N_NODES * F3];
__device__ uint16_t g_al[N_NODES * F3];
__device__ uint16_t g_wh[WTOT];
__device__ uint16_t g_wl[WTOT];
__device__ uint16_t g_ph[N_GRAPHS * F3];
__device__ uint16_t g_pl[N_GRAPHS * F3];
__device__ uint16_t g_m1h[N_GRAPHS * 1024], g_m1l[N_GRAPHS * 1024];
__device__ uint16_t g_m2h[N_GRAPHS * 1024], g_m2l[N_GRAPHS * 1024];
__device__ int     g_count[N_NODES];     // zero at load; phase3 resets each launch
__device__ float   g_dinv[N_NODES];
__device__ int     g_rowptr[N_NODES + 1];
__device__ int     g_cursor[N_NODES];
__device__ int     g_bsum[SCAN_NB];
__device__ int     g_boff[SCAN_NB];
__device__ EdgeRec g_edge[NE_TOT];
__device__ int     g_src[N_EDGES];
__device__ int     g_dst[N_EDGES];
__device__ int     g_batch[N_NODES];
__device__ int     g_gstart[N_GRAPHS + 1];
__device__ int     g_is64;

__device__ __forceinline__ void fsplit(float v, uint16_t& hi, uint16_t& lo) {
    __nv_bfloat16 h = __float2bfloat16(v);
    __nv_bfloat16 l = __float2bfloat16(v - __bfloat162float(h));
    hi = __bfloat16_as_ushort(h);
    lo = __bfloat16_as_ushort(l);
}

// ---------------- dtype detection ----------------
__global__ void detect_kernel(const int* __restrict__ ei32) {
    __shared__ int sh[256];
    int t = threadIdx.x;
    int orv = 0;
    for (int i = t; i < 2048; i += 256) orv |= ei32[2 * i + 1];
    sh[t] = orv;
    __syncthreads();
    for (int o = 128; o; o >>= 1) {
        if (t < o) sh[t] |= sh[t + o];
        __syncthreads();
    }
    if (t == 0) g_is64 = (sh[0] == 0) ? 1 : 0;
}

// ---------------- fused prep: edges+hist, batch, all weight splits ----------------
__device__ __forceinline__ void wsplit_one(const float* W, int off, int K, int N, int idx) {
    int k = idx / N, n = idx % N;
    uint16_t h, l;
    fsplit(W[idx], h, l);
    g_wh[(size_t)off + (size_t)n * K + k] = h;
    g_wl[(size_t)off + (size_t)n * K + k] = l;
}

__global__ void prep_kernel(const void* __restrict__ ei, const void* __restrict__ batch,
                            const float* __restrict__ W1, const float* __restrict__ W2,
                            const float* __restrict__ W3, const float* __restrict__ Wg1,
                            const float* __restrict__ Wg2, const float* __restrict__ Wf1,
                            const float* __restrict__ Wf2)
{
    int idx = blockIdx.x * blockDim.x + threadIdx.x;
    if (idx >= PREP_TOT) return;
    if (idx < SEG_EDGE) {
        int e = idx, s, d;
        if (g_is64) {
            const long long* p = (const long long*)ei;
            s = (int)p[e];
            d = (int)p[N_EDGES + e];
        } else {
            const int* p = (const int*)ei;
            s = p[e];
            d = p[N_EDGES + e];
        }
        g_src[e] = s;
        g_dst[e] = d;
        atomicAdd(&g_count[d], 1);
    } else if (idx < SEG_BATCH) {
        int i = idx - SEG_EDGE;
        g_batch[i] = g_is64 ? (int)((const long long*)batch)[i] : ((const int*)batch)[i];
    } else if (idx < SEG_W1)  wsplit_one(W1,  OW1,  F0,   F1,   idx - SEG_BATCH);
    else if (idx < SEG_W2)    wsplit_one(W2,  OW2,  F1,   F2,   idx - SEG_W1);
    else if (idx < SEG_W3)    wsplit_one(W3,  OW3,  F2,   F3,   idx - SEG_W2);
    else if (idx < SEG_WG1)   wsplit_one(Wg1, OWG1, F3,   1024, idx - SEG_W3);
    else if (idx < SEG_WG2)   wsplit_one(Wg2, OWG2, 1024, 128,  idx - SEG_WG1);
    else if (idx < SEG_WF1)   wsplit_one(Wf1, OWF1, 128,  1024, idx - SEG_WG2);
    else                      wsplit_one(Wf2, OWF2, 1024, 512,  idx - SEG_WF1);
}

// ---------------- parallel 3-phase scan over deg = count+1 ----------------
__global__ void scan_p1_kernel() {
    __shared__ int sh[256];
    int t = threadIdx.x;
    int i = blockIdx.x * 256 + t;
    int v = (i < N_NODES) ? g_count[i] + 1 : 0;
    sh[t] = v;
    __syncthreads();
    for (int o = 128; o; o >>= 1) {
        if (t < o) sh[t] += sh[t + o];
        __syncthreads();
    }
    if (t == 0) g_bsum[blockIdx.x] = sh[0];
}

__global__ void scan_p2_kernel() {
    __shared__ int sh[256];
    int t = threadIdx.x;
    int v = (t < SCAN_NB) ? g_bsum[t] : 0;
    sh[t] = v;
    __syncthreads();
    for (int off = 1; off < 256; off <<= 1) {
        int u = (t >= off) ? sh[t - off] : 0;
        __syncthreads();
        sh[t] += u;
        __syncthreads();
    }
    if (t < SCAN_NB) g_boff[t] = sh[t] - v;     // exclusive
    if (t == 255) g_rowptr[N_NODES] = sh[255];  // total = NE_TOT
}

// phase3: block exclusive scan + boff -> rowptr/cursor; fused dinv + count reset
__global__ void scan_p3_kernel() {
    __shared__ int sh[256];
    int t = threadIdx.x;
    int i = blockIdx.x * 256 + t;
    int v = (i < N_NODES) ? g_count[i] + 1 : 0;
    sh[t] = v;
    __syncthreads();
    for (int off = 1; off < 256; off <<= 1) {
        int u = (t >= off) ? sh[t - off] : 0;
        __syncthreads();
        sh[t] += u;
        __syncthreads();
    }
    if (i < N_NODES) {
        int r = g_boff[blockIdx.x] + sh[t] - v;  // exclusive prefix
        g_rowptr[i] = r;
        g_cursor[i] = r;
        g_dinv[i] = rsqrtf((float)v);
        g_count[i] = 0;                          // reset for next graph replay
    }
}

// fused: edges + self loops into packed EdgeRec CSR
__global__ void fill_kernel() {
    int t = blockIdx.x * blockDim.x + threadIdx.x;
    if (t >= NE_TOT) return;
    if (t < N_EDGES) {
        int s = g_src[t];
        int d = g_dst[t];
        int p = atomicAdd(&g_cursor[d], 1);
        EdgeRec r;
        r.src = s;
        r.w = g_dinv[s] * g_dinv[d];
        g_edge[p] = r;
    } else {
        int i = t - N_EDGES;
        int p = atomicAdd(&g_cursor[i], 1);
        float di = g_dinv[i];
        EdgeRec r;
        r.src = i;
        r.w = di * di;
        g_edge[p] = r;
    }
}

__global__ void gstart_kernel() {
    int i = blockIdx.x * blockDim.x + threadIdx.x;
    if (i > N_NODES) return;
    if (i == 0) {
        for (int g = 0; g <= g_batch[0]; g++) g_gstart[g] = 0;
    } else if (i == N_NODES) {
        for (int g = g_batch[N_NODES - 1] + 1; g <= N_GRAPHS; g++) g_gstart[g] = N_NODES;
    } else {
        int b0 = g_batch[i - 1], b1 = g_batch[i];
        for (int g = b0 + 1; g <= b1; g++) g_gstart[g] = i;
    }
}

// ---------------- GCN aggregation: warp per node, all F cols in registers ----------------
template <int CH>
__global__ void __launch_bounds__(256) agg_kernel_t(
    const float* __restrict__ x, uint16_t* __restrict__ ah,
    uint16_t* __restrict__ al, int F)
{
    int node = blockIdx.x * 8 + threadIdx.y;
    if (node >= N_NODES) return;
    int lane = threadIdx.x;
    int k0 = g_rowptr[node], k1 = g_rowptr[node + 1];
    float acc[CH];
    #pragma unroll
    for (int i = 0; i < CH; i++) acc[i] = 0.0f;

    const int2* ep = (const int2*)g_edge;
    #pragma unroll 2
    for (int k = k0; k < k1; k++) {
        int2 er = ep[k];
        int src = er.x;
        float w = __int_as_float(er.y);
        const float* row = x + (size_t)src * F;
        #pragma unroll
        for (int i = 0; i < CH; i++) {
            int c = i * 32 + lane;
            float v = (c < F) ? row[c] : 0.0f;
            acc[i] = fmaf(v, w, acc[i]);
        }
    }
    #pragma unroll
    for (int i = 0; i < CH; i++) {
        int c = i * 32 + lane;
        if (c < F) {
            uint16_t h, l;
            fsplit(acc[i], h, l);
            ah[(size_t)node * F + c] = h;
            al[(size_t)node * F + c] = l;
        }
    }
}

// ---------------- tensor-core GEMM, pre-split bf16 inputs ----------------
#define BM 128
#define BN 64

__device__ __forceinline__ void mma16816(float* c, const uint32_t* a, const uint32_t* b) {
    asm volatile(
        "mma.sync.aligned.m16n8k16.row.col.f32.bf16.bf16.f32 "
        "{%0,%1,%2,%3}, {%4,%5,%6,%7}, {%8,%9}, {%0,%1,%2,%3};\n"
        : "+f"(c[0]), "+f"(c[1]), "+f"(c[2]), "+f"(c[3])
        : "r"(a[0]), "r"(a[1]), "r"(a[2]), "r"(a[3]), "r"(b[0]), "r"(b[1]));
}

__global__ void __launch_bounds__(256) mma_gemm_kernel(
    const uint16_t* __restrict__ Ahp, const uint16_t* __restrict__ Alp,
    const uint16_t* __restrict__ Bhp, const uint16_t* __restrict__ Blp,
    const float* __restrict__ bias,
    float* __restrict__ Cf, uint16_t* __restrict__ Chp, uint16_t* __restrict__ Clp,
    int M, int N, int K, int relu)
{
    __shared__ uint32_t sAh[BM][9];
    __shared__ uint32_t sAl[BM][9];
    __shared__ uint32_t sBh[BN][9];
    __shared__ uint32_t sBl[BN][9];

    const uint32_t* Ah32 = (const uint32_t*)Ahp;
    const uint32_t* Al32 = (const uint32_t*)Alp;
    const uint32_t* Bh32 = (const uint32_t*)Bhp;
    const uint32_t* Bl32 = (const uint32_t*)Blp;
    int K2 = K >> 1;

    int tid = threadIdx.x;
    int warp = tid >> 5, lane = tid & 31;
    int wm = warp >> 1;
    int wn = warp & 1;
    int g = lane >> 2, tg = lane & 3;
    int rowBase = blockIdx.y * BM;
    int colBase = blockIdx.x * BN;

    float acc[2][4][4];
    #pragma unroll
    for (int mt = 0; mt < 2; mt++)
        #pragma unroll
        for (int nt = 0; nt < 4; nt++)
            #pragma unroll
            for (int i = 0; i < 4; i++) acc[mt][nt][i] = 0.0f;

    int rowA = tid >> 1;
    int kpA = (tid & 1) * 4;
    int nB = tid & 63;
    int kpB = tid >> 6;

    for (int k0 = 0; k0 < K; k0 += 16) {
        int kp0 = k0 >> 1;
        __syncthreads();
        {
            int gr = rowBase + rowA;
            bool rok = gr < M;
            size_t base = (size_t)gr * K2;
            #pragma unroll
            for (int p = 0; p < 4; p++) {
                int kp = kp0 + kpA + p;
                bool ok = rok && kp < K2;
                sAh[rowA][kpA + p] = ok ? Ah32[base + kp] : 0u;
                sAl[rowA][kpA + p] = ok ? Al32[base + kp] : 0u;
            }
        }
        {
            int gc = colBase + nB;
            bool cok = gc < N;
            size_t base = (size_t)gc * K2;
            #pragma unroll
            for (int p = 0; p < 2; p++) {
                int kpi = kpB + p * 4;
                int kp = kp0 + kpi;
                bool ok = cok && kp < K2;
                sBh[nB][kpi] = ok ? Bh32[base + kp] : 0u;
                sBl[nB][kpi] = ok ? Bl32[base + kp] : 0u;
            }
        }
        __syncthreads();

        uint32_t af[2][2][4];
        #pragma unroll
        for (int mt = 0; mt < 2; mt++) {
            int r0 = wm * 32 + mt * 16 + g;
            af[0][mt][0] = sAh[r0][tg];     af[0][mt][1] = sAh[r0 + 8][tg];
            af[0][mt][2] = sAh[r0][tg + 4]; af[0][mt][3] = sAh[r0 + 8][tg + 4];
            af[1][mt][0] = sAl[r0][tg];     af[1][mt][1] = sAl[r0 + 8][tg];
            af[1][mt][2] = sAl[r0][tg + 4]; af[1][mt][3] = sAl[r0 + 8][tg + 4];
        }
        uint32_t bfr[2][4][2];
        #pragma unroll
        for (int nt = 0; nt < 4; nt++) {
            int n0 = wn * 32 + nt * 8 + g;
            bfr[0][nt][0] = sBh[n0][tg]; bfr[0][nt][1] = sBh[n0][tg + 4];
            bfr[1][nt][0] = sBl[n0][tg]; bfr[1][nt][1] = sBl[n0][tg + 4];
        }
        #pragma unroll
        for (int mt = 0; mt < 2; mt++)
            #pragma unroll
            for (int nt = 0; nt < 4; nt++) {
                mma16816(acc[mt][nt], af[0][mt], bfr[0][nt]);
                mma16816(acc[mt][nt], af[0][mt], bfr[1][nt]);
                mma16816(acc[mt][nt], af[1][mt], bfr[0][nt]);
            }
    }

    #pragma unroll
    for (int mt = 0; mt < 2; mt++) {
        int r0 = rowBase + wm * 32 + mt * 16 + g;
        #pragma unroll
        for (int nt = 0; nt < 4; nt++) {
            int c0 = colBase + wn * 32 + nt * 8 + tg * 2;
            #pragma unroll
            for (int half = 0; half < 2; half++) {
                int r = r0 + half * 8;
                if (r >= M || c0 >= N) continue;
                float v0 = acc[mt][nt][half * 2 + 0];
                float v1 = acc[mt][nt][half * 2 + 1];
                v0 += bias[c0];
                v1 += bias[c0 + 1];
                if (relu) { v0 = fmaxf(v0, 0.0f); v1 = fmaxf(v1, 0.0f); }
                if (Cf) {
                    Cf[(size_t)r * N + c0]     = v0;
                    Cf[(size_t)r * N + c0 + 1] = v1;
                } else {
                    uint16_t h0, l0, h1, l1;
                    fsplit(v0, h0, l0);
                    fsplit(v1, h1, l1);
                    ((uint32_t*)Chp)[((size_t)r * N + c0) >> 1] = ((uint32_t)h1 << 16) | h0;
                    ((uint32_t*)Clp)[((size_t)r * N + c0) >> 1] = ((uint32_t)l1 << 16) | l0;
                }
            }
        }
    }
}

// ---------------- segmented global max pool -> split ----------------
__global__ void pool_kernel(const float* __restrict__ y)
{
    int grp = blockIdx.x * blockDim.y + threadIdx.y;
    if (grp >= N_GRAPHS) return;
    int c = blockIdx.y * 32 + threadIdx.x;
    if (c >= F3) return;
    int s = g_gstart[grp], e = g_gstart[grp + 1];
    float m = 0.0f;
    for (int i = s; i < e; i++) m = fmaxf(m, y[(size_t)i * F3 + c]);
    uint16_t h, l;
    fsplit(m, h, l);
    g_ph[(size_t)grp * F3 + c] = h;
    g_pl[(size_t)grp * F3 + c] = l;
}

// ---------------- final 512 -> 1 dot + sigmoid ----------------
__global__ void final_kernel(const float* __restrict__ Wo,
                             const float* __restrict__ bo, float* __restrict__ out)
{
    int row = blockIdx.x * blockDim.y + threadIdx.y;
    if (row >= N_GRAPHS) return;
    int lane = threadIdx.x;
    float s = 0.0f;
    for (int k = lane; k < 512; k += 32) {
        float v = __bfloat162float(__ushort_as_bfloat16(g_m2h[(size_t)row * 512 + k]))
                + __bfloat162float(__ushort_as_bfloat16(g_m2l[(size_t)row * 512 + k]));
        s = fmaf(v, Wo[k], s);
    }
    #pragma unroll
    for (int o = 16; o; o >>= 1) s += __shfl_xor_sync(0xFFFFFFFFu, s, o);
    if (lane == 0) out[row] = 1.0f / (1.0f + expf(-(s + bo[0])));
}

// ---------------- launch ----------------
extern "C" void kernel_launch(void* const* d_in, const int* in_sizes, int n_in,
                              void* d_out, int out_size)
{
    const float* x     = (const float*)d_in[0];
    const void*  ei    = d_in[1];
    const void*  batch = d_in[2];
    const float* W1 = (const float*)d_in[3];  const float* b1 = (const float*)d_in[4];
    const float* W2 = (const float*)d_in[5];  const float* b2 = (const float*)d_in[6];
    const float* W3 = (const float*)d_in[7];  const float* b3 = (const float*)d_in[8];
    const float* Wg1 = (const float*)d_in[9];  const float* bg1 = (const float*)d_in[10];
    const float* Wg2 = (const float*)d_in[11]; const float* bg2 = (const float*)d_in[12];
    const float* Wf1 = (const float*)d_in[13]; const float* bf1 = (const float*)d_in[14];
    const float* Wf2 = (const float*)d_in[15]; const float* bf2 = (const float*)d_in[16];
    const float* Wo  = (const float*)d_in[17]; const float* bo  = (const float*)d_in[18];
    float* out = (float*)d_out;

    float *y;
    uint16_t *ah, *al, *wh, *wl, *ph, *pl, *m1h, *m1l, *m2h, *m2l;
    cudaGetSymbolAddress((void**)&y,   g_y);
    cudaGetSymbolAddress((void**)&ah,  g_ah);
    cudaGetSymbolAddress((void**)&al,  g_al);
    cudaGetSymbolAddress((void**)&wh,  g_wh);
    cudaGetSymbolAddress((void**)&wl,  g_wl);
    cudaGetSymbolAddress((void**)&ph,  g_ph);
    cudaGetSymbolAddress((void**)&pl,  g_pl);
    cudaGetSymbolAddress((void**)&m1h, g_m1h);
    cudaGetSymbolAddress((void**)&m1l, g_m1l);
    cudaGetSymbolAddress((void**)&m2h, g_m2h);
    cudaGetSymbolAddress((void**)&m2l, g_m2l);

    // preprocessing
    detect_kernel<<<1, 256>>>((const int*)ei);
    prep_kernel<<<(PREP_TOT + 255) / 256, 256>>>(ei, batch, W1, W2, W3, Wg1, Wg2, Wf1, Wf2);
    scan_p1_kernel<<<SCAN_NB, 256>>>();
    scan_p2_kernel<<<1, 256>>>();
    scan_p3_kernel<<<SCAN_NB, 256>>>();
    fill_kernel<<<(NE_TOT + 255) / 256, 256>>>();

    auto gemm = [&](const uint16_t* Ah, const uint16_t* Al, int woff,
                    const float* bias, float* Cf, uint16_t* Ch, uint16_t* Cl,
                    int M, int N, int K, int relu) {
        dim3 grid((N + BN - 1) / BN, (M + BM - 1) / BM);
        mma_gemm_kernel<<<grid, 256>>>(Ah, Al, wh + woff, wl + woff, bias,
                                       Cf, Ch, Cl, M, N, K, relu);
    };
    dim3 cb(32, 8);

    // layer 1 (agg over F0=78 -> 3 chunks)
    agg_kernel_t<3><<<(N_NODES + 7) / 8, cb>>>(x, ah, al, F0);
    gemm(ah, al, OW1, b1, y, nullptr, nullptr, N_NODES, F1, F0, 1);
    // layer 2 (F1=78 -> 3 chunks)
    agg_kernel_t<3><<<(N_NODES + 7) / 8, cb>>>(y, ah, al, F1);
    gemm(ah, al, OW2, b2, y, nullptr, nullptr, N_NODES, F2, F1, 1);
    // layer 3 (F2=156 -> 5 chunks)
    agg_kernel_t<5><<<(N_NODES + 7) / 8, cb>>>(y, ah, al, F2);
    gemm(ah, al, OW3, b3, y, nullptr, nullptr, N_NODES, F3, F2, 1);

    // pool
    gstart_kernel<<<(N_NODES + 256) / 256, 256>>>();
    pool_kernel<<<dim3((N_GRAPHS + 7) / 8, (F3 + 31) / 32), cb>>>(y);

    // MLP head
    gemm(ph, pl,   OWG1, bg1, nullptr, m1h, m1l, N_GRAPHS, 1024, F3,  1);
    gemm(m1h, m1l, OWG2, bg2, nullptr, m2h, m2l, N_GRAPHS, 128, 1024, 0);
    gemm(m2h, m2l, OWF1, bf1, nullptr, m1h, m1l, N_GRAPHS, 1024, 128, 1);
    gemm(m1h, m1l, OWF2, bf2, nullptr, m2h, m2l, N_GRAPHS, 512, 1024, 1);
    final_kernel<<<(N_GRAPHS + 7) / 8, cb>>>(Wo, bo, out);
}

// round 7
// speedup vs baseline: 1.9880x; 1.2807x over previous
#include <cuda_runtime.h>
#include <cuda_bf16.h>
#include <math.h>
#include <stdint.h>

#define N_NODES  50000
#define N_EDGES  800000
#define N_GRAPHS 2048
#define NE_TOT   (N_EDGES + N_NODES)
#define F0 78
#define F1 78
#define F2 156
#define F3 312

#define SCAN_NB ((N_NODES + 255) / 256)   // 196

// padded stride (uint16 elements): multiple of 16
#define KP16(K) (((K) + 15) & ~15)
#define FP0 KP16(F0)    // 80
#define FP2 KP16(F2)    // 160
#define FP3 KP16(F3)    // 320

// weight split-transpose offsets ([N][KP16] layout, bf16 hi/lo), all 16B-aligned
#define OW1  0
#define OW2  (OW1 + F1 * KP16(F0))            // 78*80   = 6240
#define OW3  (OW2 + F2 * KP16(F1))            // 156*80  = 12480
#define OWG1 (OW3 + F3 * KP16(F2))            // 312*160 = 49920
#define OWG2 (OWG1 + 1024 * KP16(F3))         // 1024*320= 327680
#define OWF1 (OWG2 + 128 * 1024)
#define OWF2 (OWF1 + 1024 * 128)
#define WTOT (OWF2 + 512 * 1024)

#define SEG_EDGE  N_EDGES
#define SEG_BATCH (SEG_EDGE + N_NODES)
#define NW1  (F0 * F1)
#define NW2  (F1 * F2)
#define NW3  (F2 * F3)
#define NWG1 (F3 * 1024)
#define NWG2 (1024 * 128)
#define NWF1 (128 * 1024)
#define NWF2 (1024 * 512)
#define SEG_W1  (SEG_BATCH + NW1)
#define SEG_W2  (SEG_W1 + NW2)
#define SEG_W3  (SEG_W2 + NW3)
#define SEG_WG1 (SEG_W3 + NWG1)
#define SEG_WG2 (SEG_WG1 + NWG2)
#define SEG_WF1 (SEG_WG2 + NWF1)
#define SEG_WF2 (SEG_WF1 + NWF2)
#define PREP_TOT SEG_WF2

struct EdgeRec { int src; float w; };

// ---------------- scratch (device globals; zero-initialized at module load) ----------------
__device__ float    g_y[N_NODES * F3];
__device__ __align__(16) uint16_t g_ah[N_NODES * FP2];   // padded split activations
__device__ __align__(16) uint16_t g_al[N_NODES * FP2];
__device__ __align__(16) uint16_t g_wh[WTOT];
__device__ __align__(16) uint16_t g_wl[WTOT];
__device__ __align__(16) uint16_t g_ph[N_GRAPHS * FP3];
__device__ __align__(16) uint16_t g_pl[N_GRAPHS * FP3];
__device__ __align__(16) uint16_t g_m1h[N_GRAPHS * 1024], g_m1l[N_GRAPHS * 1024];
__device__ __align__(16) uint16_t g_m2h[N_GRAPHS * 1024], g_m2l[N_GRAPHS * 1024];
__device__ int     g_count[N_NODES];     // zero at load; phase3 resets each launch
__device__ float   g_dinv[N_NODES];
__device__ int     g_rowptr[N_NODES + 1];
__device__ int     g_cursor[N_NODES];
__device__ int     g_bsum[SCAN_NB];
__device__ int     g_boff[SCAN_NB];
__device__ EdgeRec g_edge[NE_TOT];
__device__ int     g_src[N_EDGES];
__device__ int     g_dst[N_EDGES];
__device__ int     g_batch[N_NODES];
__device__ int     g_gstart[N_GRAPHS + 1];
__device__ int     g_is64;

__device__ __forceinline__ void fsplit(float v, uint16_t& hi, uint16_t& lo) {
    __nv_bfloat16 h = __float2bfloat16(v);
    __nv_bfloat16 l = __float2bfloat16(v - __bfloat162float(h));
    hi = __bfloat16_as_ushort(h);
    lo = __bfloat16_as_ushort(l);
}

// ---------------- dtype detection ----------------
__global__ void detect_kernel(const int* __restrict__ ei32) {
    __shared__ int sh[256];
    int t = threadIdx.x;
    int orv = 0;
    for (int i = t; i < 2048; i += 256) orv |= ei32[2 * i + 1];
    sh[t] = orv;
    __syncthreads();
    for (int o = 128; o; o >>= 1) {
        if (t < o) sh[t] |= sh[t + o];
        __syncthreads();
    }
    if (t == 0) g_is64 = (sh[0] == 0) ? 1 : 0;
}

// ---------------- fused prep: edges+hist, batch, all weight splits ----------------
__device__ __forceinline__ void wsplit_one(const float* W, int off, int K, int N,
                                           int kp16, int idx) {
    int k = idx / N, n = idx % N;
    uint16_t h, l;
    fsplit(W[idx], h, l);
    g_wh[(size_t)off + (size_t)n * kp16 + k] = h;
    g_wl[(size_t)off + (size_t)n * kp16 + k] = l;
}

__global__ void prep_kernel(const void* __restrict__ ei, const void* __restrict__ batch,
                            const float* __restrict__ W1, const float* __restrict__ W2,
                            const float* __restrict__ W3, const float* __restrict__ Wg1,
                            const float* __restrict__ Wg2, const float* __restrict__ Wf1,
                            const float* __restrict__ Wf2)
{
    int idx = blockIdx.x * blockDim.x + threadIdx.x;
    if (idx >= PREP_TOT) return;
    if (idx < SEG_EDGE) {
        int e = idx, s, d;
        if (g_is64) {
            const long long* p = (const long long*)ei;
            s = (int)p[e];
            d = (int)p[N_EDGES + e];
        } else {
            const int* p = (const int*)ei;
            s = p[e];
            d = p[N_EDGES + e];
        }
        g_src[e] = s;
        g_dst[e] = d;
        atomicAdd(&g_count[d], 1);
    } else if (idx < SEG_BATCH) {
        int i = idx - SEG_EDGE;
        g_batch[i] = g_is64 ? (int)((const long long*)batch)[i] : ((const int*)batch)[i];
    } else if (idx < SEG_W1)  wsplit_one(W1,  OW1,  F0,   F1,   KP16(F0),  idx - SEG_BATCH);
    else if (idx < SEG_W2)    wsplit_one(W2,  OW2,  F1,   F2,   KP16(F1),  idx - SEG_W1);
    else if (idx < SEG_W3)    wsplit_one(W3,  OW3,  F2,   F3,   KP16(F2),  idx - SEG_W2);
    else if (idx < SEG_WG1)   wsplit_one(Wg1, OWG1, F3,   1024, KP16(F3),  idx - SEG_W3);
    else if (idx < SEG_WG2)   wsplit_one(Wg2, OWG2, 1024, 128,  1024,      idx - SEG_WG1);
    else if (idx < SEG_WF1)   wsplit_one(Wf1, OWF1, 128,  1024, 128,       idx - SEG_WG2);
    else                      wsplit_one(Wf2, OWF2, 1024, 512,  1024,      idx - SEG_WF1);
}

// ---------------- parallel 3-phase scan over deg = count+1 ----------------
__global__ void scan_p1_kernel() {
    __shared__ int sh[256];
    int t = threadIdx.x;
    int i = blockIdx.x * 256 + t;
    int v = (i < N_NODES) ? g_count[i] + 1 : 0;
    sh[t] = v;
    __syncthreads();
    for (int o = 128; o; o >>= 1) {
        if (t < o) sh[t] += sh[t + o];
        __syncthreads();
    }
    if (t == 0) g_bsum[blockIdx.x] = sh[0];
}

__global__ void scan_p2_kernel() {
    __shared__ int sh[256];
    int t = threadIdx.x;
    int v = (t < SCAN_NB) ? g_bsum[t] : 0;
    sh[t] = v;
    __syncthreads();
    for (int off = 1; off < 256; off <<= 1) {
        int u = (t >= off) ? sh[t - off] : 0;
        __syncthreads();
        sh[t] += u;
        __syncthreads();
    }
    if (t < SCAN_NB) g_boff[t] = sh[t] - v;
    if (t == 255) g_rowptr[N_NODES] = sh[255];
}

__global__ void scan_p3_kernel() {
    __shared__ int sh[256];
    int t = threadIdx.x;
    int i = blockIdx.x * 256 + t;
    int v = (i < N_NODES) ? g_count[i] + 1 : 0;
    sh[t] = v;
    __syncthreads();
    for (int off = 1; off < 256; off <<= 1) {
        int u = (t >= off) ? sh[t - off] : 0;
        __syncthreads();
        sh[t] += u;
        __syncthreads();
    }
    if (i < N_NODES) {
        int r = g_boff[blockIdx.x] + sh[t] - v;
        g_rowptr[i] = r;
        g_cursor[i] = r;
        g_dinv[i] = rsqrtf((float)v);
        g_count[i] = 0;
    }
}

__global__ void fill_kernel() {
    int t = blockIdx.x * blockDim.x + threadIdx.x;
    if (t >= NE_TOT) return;
    if (t < N_EDGES) {
        int s = g_src[t];
        int d = g_dst[t];
        int p = atomicAdd(&g_cursor[d], 1);
        EdgeRec r;
        r.src = s;
        r.w = g_dinv[s] * g_dinv[d];
        g_edge[p] = r;
    } else {
        int i = t - N_EDGES;
        int p = atomicAdd(&g_cursor[i], 1);
        float di = g_dinv[i];
        EdgeRec r;
        r.src = i;
        r.w = di * di;
        g_edge[p] = r;
    }
}

__global__ void gstart_kernel() {
    int i = blockIdx.x * blockDim.x + threadIdx.x;
    if (i > N_NODES) return;
    if (i == 0) {
        for (int g = 0; g <= g_batch[0]; g++) g_gstart[g] = 0;
    } else if (i == N_NODES) {
        for (int g = g_batch[N_NODES - 1] + 1; g <= N_GRAPHS; g++) g_gstart[g] = N_NODES;
    } else {
        int b0 = g_batch[i - 1], b1 = g_batch[i];
        for (int g = b0 + 1; g <= b1; g++) g_gstart[g] = i;
    }
}

// ---------------- GCN aggregation: warp per node; writes padded split ----------------
template <int CH>
__global__ void __launch_bounds__(256) agg_kernel_t(
    const float* __restrict__ x, uint16_t* __restrict__ ah,
    uint16_t* __restrict__ al, int F, int FP)
{
    int node = blockIdx.x * 8 + threadIdx.y;
    if (node >= N_NODES) return;
    int lane = threadIdx.x;
    int k0 = g_rowptr[node], k1 = g_rowptr[node + 1];
    float acc[CH];
    #pragma unroll
    for (int i = 0; i < CH; i++) acc[i] = 0.0f;

    const int2* ep = (const int2*)g_edge;
    #pragma unroll 2
    for (int k = k0; k < k1; k++) {
        int2 er = ep[k];
        int src = er.x;
        float w = __int_as_float(er.y);
        const float* row = x + (size_t)src * F;
        #pragma unroll
        for (int i = 0; i < CH; i++) {
            int c = i * 32 + lane;
            float v = (c < F) ? row[c] : 0.0f;
            acc[i] = fmaf(v, w, acc[i]);
        }
    }
    #pragma unroll
    for (int i = 0; i < CH; i++) {
        int c = i * 32 + lane;
        if (c < F) {
            uint16_t h, l;
            fsplit(acc[i], h, l);
            ah[(size_t)node * FP + c] = h;
            al[(size_t)node * FP + c] = l;
        }
    }
}

// ---------------- tensor-core GEMM, padded split inputs, vectorized loads ----------------
#define BM 128
#define BN 64

__device__ __forceinline__ void mma16816(float* c, const uint32_t* a, const uint32_t* b) {
    asm volatile(
        "mma.sync.aligned.m16n8k16.row.col.f32.bf16.bf16.f32 "
        "{%0,%1,%2,%3}, {%4,%5,%6,%7}, {%8,%9}, {%0,%1,%2,%3};\n"
        : "+f"(c[0]), "+f"(c[1]), "+f"(c[2]), "+f"(c[3])
        : "r"(a[0]), "r"(a[1]), "r"(a[2]), "r"(a[3]), "r"(b[0]), "r"(b[1]));
}

// A: [M][K2P] uint32 (padded, pad=0). B: [N][K2P] uint32 (padded, pad=0).
__global__ void __launch_bounds__(256) mma_gemm_kernel(
    const uint32_t* __restrict__ Ah32, const uint32_t* __restrict__ Al32,
    const uint32_t* __restrict__ Bh32, const uint32_t* __restrict__ Bl32,
    const float* __restrict__ bias,
    float* __restrict__ Cf, uint32_t* __restrict__ Ch32, uint32_t* __restrict__ Cl32,
    int M, int N, int K, int K2P, int relu)
{
    __shared__ uint32_t sAh[BM][9];
    __shared__ uint32_t sAl[BM][9];
    __shared__ uint32_t sBh[BN][9];
    __shared__ uint32_t sBl[BN][9];

    int tid = threadIdx.x;
    int warp = tid >> 5, lane = tid & 31;
    int wm = warp >> 1;
    int wn = warp & 1;
    int g = lane >> 2, tg = lane & 3;
    int rowBase = blockIdx.y * BM;
    int colBase = blockIdx.x * BN;

    float acc[2][4][4];
    #pragma unroll
    for (int mt = 0; mt < 2; mt++)
        #pragma unroll
        for (int nt = 0; nt < 4; nt++)
            #pragma unroll
            for (int i = 0; i < 4; i++) acc[mt][nt][i] = 0.0f;

    // load roles
    int rowA = tid >> 1;           // 0..127
    int halfA = tid & 1;           // which uint4 of the 32B row-slice
    int nB = (tid & 127) >> 1;     // 0..63
    int halfB = tid & 1;
    bool isH = tid < 128;          // low half loads Bh, high half loads Bl

    bool aok = (rowBase + rowA) < M;
    bool bok = (colBase + nB) < N;
    const uint32_t* Aph = Ah32 + (size_t)(rowBase + rowA) * K2P + halfA * 4;
    const uint32_t* Apl = Al32 + (size_t)(rowBase + rowA) * K2P + halfA * 4;
    const uint32_t* Bp  = (isH ? Bh32 : Bl32) + (size_t)(colBase + nB) * K2P + halfB * 4;

    uint4 ra_h, ra_l, rb;
    const uint4 z4 = make_uint4(0u, 0u, 0u, 0u);
    // preload tile 0
    ra_h = aok ? *(const uint4*)(Aph) : z4;
    ra_l = aok ? *(const uint4*)(Apl) : z4;
    rb   = bok ? *(const uint4*)(Bp)  : z4;

    for (int k0 = 0; k0 < K; k0 += 16) {
        __syncthreads();
        // store prefetched regs to smem
        int ka = halfA * 4;
        sAh[rowA][ka] = ra_h.x; sAh[rowA][ka + 1] = ra_h.y;
        sAh[rowA][ka + 2] = ra_h.z; sAh[rowA][ka + 3] = ra_h.w;
        sAl[rowA][ka] = ra_l.x; sAl[rowA][ka + 1] = ra_l.y;
        sAl[rowA][ka + 2] = ra_l.z; sAl[rowA][ka + 3] = ra_l.w;
        int kb = halfB * 4;
        if (isH) {
            sBh[nB][kb] = rb.x; sBh[nB][kb + 1] = rb.y;
            sBh[nB][kb + 2] = rb.z; sBh[nB][kb + 3] = rb.w;
        } else {
            sBl[nB][kb] = rb.x; sBl[nB][kb + 1] = rb.y;
            sBl[nB][kb + 2] = rb.z; sBl[nB][kb + 3] = rb.w;
        }
        __syncthreads();
        // issue next tile's loads (overlap with mma below)
        if (k0 + 16 < K) {
            int kp = (k0 + 16) >> 1;
            ra_h = aok ? *(const uint4*)(Aph + kp) : z4;
            ra_l = aok ? *(const uint4*)(Apl + kp) : z4;
            rb   = bok ? *(const uint4*)(Bp + kp)  : z4;
        }

        uint32_t af[2][2][4];
        #pragma unroll
        for (int mt = 0; mt < 2; mt++) {
            int r0 = wm * 32 + mt * 16 + g;
            af[0][mt][0] = sAh[r0][tg];     af[0][mt][1] = sAh[r0 + 8][tg];
            af[0][mt][2] = sAh[r0][tg + 4]; af[0][mt][3] = sAh[r0 + 8][tg + 4];
            af[1][mt][0] = sAl[r0][tg];     af[1][mt][1] = sAl[r0 + 8][tg];
            af[1][mt][2] = sAl[r0][tg + 4]; af[1][mt][3] = sAl[r0 + 8][tg + 4];
        }
        uint32_t bfr[2][4][2];
        #pragma unroll
        for (int nt = 0; nt < 4; nt++) {
            int n0 = wn * 32 + nt * 8 + g;
            bfr[0][nt][0] = sBh[n0][tg]; bfr[0][nt][1] = sBh[n0][tg + 4];
            bfr[1][nt][0] = sBl[n0][tg]; bfr[1][nt][1] = sBl[n0][tg + 4];
        }
        #pragma unroll
        for (int mt = 0; mt < 2; mt++)
            #pragma unroll
            for (int nt = 0; nt < 4; nt++) {
                mma16816(acc[mt][nt], af[0][mt], bfr[0][nt]);
                mma16816(acc[mt][nt], af[0][mt], bfr[1][nt]);
                mma16816(acc[mt][nt], af[1][mt], bfr[0][nt]);
            }
    }

    #pragma unroll
    for (int mt = 0; mt < 2; mt++) {
        int r0 = rowBase + wm * 32 + mt * 16 + g;
        #pragma unroll
        for (int nt = 0; nt < 4; nt++) {
            int c0 = colBase + wn * 32 + nt * 8 + tg * 2;
            #pragma unroll
            for (int half = 0; half < 2; half++) {
                int r = r0 + half * 8;
                if (r >= M || c0 >= N) continue;
                float v0 = acc[mt][nt][half * 2 + 0];
                float v1 = acc[mt][nt][half * 2 + 1];
                v0 += bias[c0];
                v1 += bias[c0 + 1];
                if (relu) { v0 = fmaxf(v0, 0.0f); v1 = fmaxf(v1, 0.0f); }
                if (Cf) {
                    float2 v2 = make_float2(v0, v1);
                    *(float2*)(Cf + (size_t)r * N + c0) = v2;
                } else {
                    uint16_t h0, l0, h1, l1;
                    fsplit(v0, h0, l0);
                    fsplit(v1, h1, l1);
                    Ch32[((size_t)r * N + c0) >> 1] = ((uint32_t)h1 << 16) | h0;
                    Cl32[((size_t)r * N + c0) >> 1] = ((uint32_t)l1 << 16) | l0;
                }
            }
        }
    }
}

// ---------------- segmented global max pool -> padded split ----------------
__global__ void pool_kernel(const float* __restrict__ y)
{
    int grp = blockIdx.x * blockDim.y + threadIdx.y;
    if (grp >= N_GRAPHS) return;
    int c = blockIdx.y * 32 + threadIdx.x;
    if (c >= F3) return;
    int s = g_gstart[grp], e = g_gstart[grp + 1];
    float m = 0.0f;
    for (int i = s; i < e; i++) m = fmaxf(m, y[(size_t)i * F3 + c]);
    uint16_t h, l;
    fsplit(m, h, l);
    g_ph[(size_t)grp * FP3 + c] = h;
    g_pl[(size_t)grp * FP3 + c] = l;
}

// ---------------- final 512 -> 1 dot + sigmoid ----------------
__global__ void final_kernel(const float* __restrict__ Wo,
                             const float* __restrict__ bo, float* __restrict__ out)
{
    int row = blockIdx.x * blockDim.y + threadIdx.y;
    if (row >= N_GRAPHS) return;
    int lane = threadIdx.x;
    float s = 0.0f;
    for (int k = lane; k < 512; k += 32) {
        float v = __bfloat162float(__ushort_as_bfloat16(g_m2h[(size_t)row * 512 + k]))
                + __bfloat162float(__ushort_as_bfloat16(g_m2l[(size_t)row * 512 + k]));
        s = fmaf(v, Wo[k], s);
    }
    #pragma unroll
    for (int o = 16; o; o >>= 1) s += __shfl_xor_sync(0xFFFFFFFFu, s, o);
    if (lane == 0) out[row] = 1.0f / (1.0f + expf(-(s + bo[0])));
}

// ---------------- launch ----------------
extern "C" void kernel_launch(void* const* d_in, const int* in_sizes, int n_in,
                              void* d_out, int out_size)
{
    const float* x     = (const float*)d_in[0];
    const void*  ei    = d_in[1];
    const void*  batch = d_in[2];
    const float* W1 = (const float*)d_in[3];  const float* b1 = (const float*)d_in[4];
    const float* W2 = (const float*)d_in[5];  const float* b2 = (const float*)d_in[6];
    const float* W3 = (const float*)d_in[7];  const float* b3 = (const float*)d_in[8];
    const float* Wg1 = (const float*)d_in[9];  const float* bg1 = (const float*)d_in[10];
    const float* Wg2 = (const float*)d_in[11]; const float* bg2 = (const float*)d_in[12];
    const float* Wf1 = (const float*)d_in[13]; const float* bf1 = (const float*)d_in[14];
    const float* Wf2 = (const float*)d_in[15]; const float* bf2 = (const float*)d_in[16];
    const float* Wo  = (const float*)d_in[17]; const float* bo  = (const float*)d_in[18];
    float* out = (float*)d_out;

    float *y;
    uint16_t *ah, *al, *wh, *wl, *ph, *pl, *m1h, *m1l, *m2h, *m2l;
    cudaGetSymbolAddress((void**)&y,   g_y);
    cudaGetSymbolAddress((void**)&ah,  g_ah);
    cudaGetSymbolAddress((void**)&al,  g_al);
    cudaGetSymbolAddress((void**)&wh,  g_wh);
    cudaGetSymbolAddress((void**)&wl,  g_wl);
    cudaGetSymbolAddress((void**)&ph,  g_ph);
    cudaGetSymbolAddress((void**)&pl,  g_pl);
    cudaGetSymbolAddress((void**)&m1h, g_m1h);
    cudaGetSymbolAddress((void**)&m1l, g_m1l);
    cudaGetSymbolAddress((void**)&m2h, g_m2h);
    cudaGetSymbolAddress((void**)&m2l, g_m2l);

    // preprocessing
    detect_kernel<<<1, 256>>>((const int*)ei);
    prep_kernel<<<(PREP_TOT + 255) / 256, 256>>>(ei, batch, W1, W2, W3, Wg1, Wg2, Wf1, Wf2);
    scan_p1_kernel<<<SCAN_NB, 256>>>();
    scan_p2_kernel<<<1, 256>>>();
    scan_p3_kernel<<<SCAN_NB, 256>>>();
    fill_kernel<<<(NE_TOT + 255) / 256, 256>>>();

    auto gemm = [&](const uint16_t* Ah, const uint16_t* Al, int woff,
                    const float* bias, float* Cf, uint16_t* Ch, uint16_t* Cl,
                    int M, int N, int K, int K2P, int relu) {
        dim3 grid((N + BN - 1) / BN, (M + BM - 1) / BM);
        mma_gemm_kernel<<<grid, 256>>>((const uint32_t*)Ah, (const uint32_t*)Al,
                                       (const uint32_t*)(wh + woff), (const uint32_t*)(wl + woff),
                                       bias, Cf, (uint32_t*)Ch, (uint32_t*)Cl,
                                       M, N, K, K2P, relu);
    };
    dim3 cb(32, 8);

    // layer 1 (F0=78, FP0=80, K2P=40)
    agg_kernel_t<3><<<(N_NODES + 7) / 8, cb>>>(x, ah, al, F0, FP0);
    gemm(ah, al, OW1, b1, y, nullptr, nullptr, N_NODES, F1, F0, FP0 / 2, 1);
    // layer 2 (F1=78)
    agg_kernel_t<3><<<(N_NODES + 7) / 8, cb>>>(y, ah, al, F1, FP0);
    gemm(ah, al, OW2, b2, y, nullptr, nullptr, N_NODES, F2, F1, FP0 / 2, 1);
    // layer 3 (F2=156, FP2=160, K2P=80)
    agg_kernel_t<5><<<(N_NODES + 7) / 8, cb>>>(y, ah, al, F2, FP2);
    gemm(ah, al, OW3, b3, y, nullptr, nullptr, N_NODES, F3, F2, FP2 / 2, 1);

    // pool (FP3=320)
    gstart_kernel<<<(N_NODES + 256) / 256, 256>>>();
    pool_kernel<<<dim3((N_GRAPHS + 7) / 8, (F3 + 31) / 32), cb>>>(y);

    // MLP head
    gemm(ph,  pl,  OWG1, bg1, nullptr, m1h, m1l, N_GRAPHS, 1024, F3,   FP3 / 2, 1);
    gemm(m1h, m1l, OWG2, bg2, nullptr, m2h, m2l, N_GRAPHS, 128,  1024, 512,     0);
    gemm(m2h, m2l, OWF1, bf1, nullptr, m1h, m1l, N_GRAPHS, 1024, 128,  64,      1);
    gemm(m1h, m1l, OWF2, bf2, nullptr, m2h, m2l, N_GRAPHS, 512,  1024, 512,     1);
    final_kernel<<<(N_GRAPHS + 7) / 8, cb>>>(Wo, bo, out);
}